// round 8
// baseline (speedup 1.0000x reference)
#include <cuda_runtime.h>
#include <cstdint>

#define BATCH  32
#define SMAX   222
#define S1     197
#define DMODEL 768
#define NLAYER 12
#define NHEAD  12
#define HDIM   64
#define MLPD   3072
#define POOL   10
#define SEL    5
#define PLEN   5
#define NCLS   100
#define PSTRIDE 224

// ---------------- scratch (static device allocations; harness-legal) ----------------
__device__ float g_x   [BATCH * SMAX * DMODEL];
__device__ float g_x0  [BATCH * S1   * DMODEL];
__device__ float g_h   [BATCH * SMAX * DMODEL];
__device__ float g_qkv [BATCH * SMAX * 3 * DMODEL];
__device__ float g_o   [BATCH * SMAX * DMODEL];
__device__ float g_mlp [BATCH * SMAX * MLPD];
__device__ float g_p   [BATCH * NHEAD * PSTRIDE * PSTRIDE];
__device__ float g_feat[BATCH * DMODEL];
__device__ float g_score[BATCH * POOL];
__device__ float g_lognorm[POOL];
__device__ float g_logwn[POOL];
__device__ int   g_topk[BATCH * SEL];

// tf32-pre-rounded weight copies (converted once per launch)
__device__ float g_wq [NLAYER * DMODEL * 3 * DMODEL];   // 21.2M
__device__ float g_wp [NLAYER * DMODEL * DMODEL];       // 7.1M
__device__ float g_w1 [NLAYER * DMODEL * MLPD];         // 28.3M
__device__ float g_w2 [NLAYER * MLPD * DMODEL];         // 28.3M
__device__ float g_wpc[DMODEL * DMODEL];                // 0.6M

// ---------------- reductions (blockDim == 256 assumed) ----------------
__device__ __forceinline__ float block_sum256(float v, float* red) {
    int lane = threadIdx.x & 31, wid = threadIdx.x >> 5;
    #pragma unroll
    for (int o = 16; o; o >>= 1) v += __shfl_xor_sync(0xffffffffu, v, o);
    if (lane == 0) red[wid] = v;
    __syncthreads();
    float r = (lane < 8) ? red[lane] : 0.f;
    #pragma unroll
    for (int o = 4; o; o >>= 1) r += __shfl_xor_sync(0xffffffffu, r, o);
    r = __shfl_sync(0xffffffffu, r, 0);
    __syncthreads();
    return r;
}

__device__ __forceinline__ float block_max256(float v, float* red) {
    int lane = threadIdx.x & 31, wid = threadIdx.x >> 5;
    #pragma unroll
    for (int o = 16; o; o >>= 1) v = fmaxf(v, __shfl_xor_sync(0xffffffffu, v, o));
    if (lane == 0) red[wid] = v;
    __syncthreads();
    float r = (lane < 8) ? red[lane] : -1e30f;
    #pragma unroll
    for (int o = 4; o; o >>= 1) r = fmaxf(r, __shfl_xor_sync(0xffffffffu, r, o));
    r = __shfl_sync(0xffffffffu, r, 0);
    __syncthreads();
    return r;
}

// ---------------- tf32 helpers ----------------
__device__ __forceinline__ uint32_t f2tf32(float x) {
    uint32_t u;
    asm("cvt.rna.tf32.f32 %0, %1;" : "=r"(u) : "f"(x));
    return u;
}
__device__ __forceinline__ float rnd_tf32(float x) { return __uint_as_float(f2tf32(x)); }

__device__ __forceinline__ void mma_tf32(float* c, const uint32_t* a, uint32_t b0, uint32_t b1) {
    asm volatile(
        "mma.sync.aligned.m16n8k8.row.col.f32.tf32.tf32.f32 "
        "{%0,%1,%2,%3}, {%4,%5,%6,%7}, {%8,%9}, {%0,%1,%2,%3};"
        : "+f"(c[0]), "+f"(c[1]), "+f"(c[2]), "+f"(c[3])
        : "r"(a[0]), "r"(a[1]), "r"(a[2]), "r"(a[3]), "r"(b0), "r"(b1));
}

__device__ __forceinline__ void cp_async16(void* smem_dst, const void* gsrc, int src_bytes) {
    unsigned sa = (unsigned)__cvta_generic_to_shared(smem_dst);
    asm volatile("cp.async.cg.shared.global [%0], [%1], 16, %2;"
                 :: "r"(sa), "l"(gsrc), "r"(src_bytes));
}
__device__ __forceinline__ void cp_commit() {
    asm volatile("cp.async.commit_group;");
}

// weight pre-round: dst = tf32(src), vectorized
__global__ void round_tf32_kernel(const float* __restrict__ src, float* __restrict__ dst, long long n)
{
    long long i = ((long long)blockIdx.x * 256 + threadIdx.x) * 4;
    if (i + 3 < n) {
        float4 v = *reinterpret_cast<const float4*>(&src[i]);
        v.x = rnd_tf32(v.x); v.y = rnd_tf32(v.y); v.z = rnd_tf32(v.z); v.w = rnd_tf32(v.w);
        *reinterpret_cast<float4*>(&dst[i]) = v;
    } else {
        for (; i < n; i++) dst[i] = rnd_tf32(src[i]);
    }
}

// ---------------- pipelined tf32 tensor-core GEMM ----------------
// Inputs A and W are ALREADY tf32-rounded. C = A@W + bias.
// mode 0 = store, 1 = GELU store (tf32-rounded), 2 = add into C
#define TBM 128
#define TBN 128
#define TBK 32
#define APITCH 36
#define WPITCH 136
#define GEMM_SMEM ((2 * TBM * APITCH + 2 * TBK * WPITCH) * 4)

__global__ void __launch_bounds__(256, 2) tc_gemm_kernel(
    const float* __restrict__ A, const float* __restrict__ W,
    const float* __restrict__ bias, float* __restrict__ C,
    int M, int N, int K, int mode)
{
    extern __shared__ float smem[];
    float* As = smem;                       // [2][TBM][APITCH]
    float* Ws = smem + 2 * TBM * APITCH;    // [2][TBK][WPITCH]

    int tid  = threadIdx.x;
    int warp = tid >> 5, lane = tid & 31;
    int g = lane >> 2, tig = lane & 3;
    int wm = (warp & 1) * 64;
    int wn = (warp >> 1) * 32;
    int row0 = blockIdx.y * TBM;
    int col0 = blockIdx.x * TBN;

    float acc[4][4][4];
    #pragma unroll
    for (int mt = 0; mt < 4; mt++)
        #pragma unroll
        for (int nt = 0; nt < 4; nt++)
            #pragma unroll
            for (int i = 0; i < 4; i++) acc[mt][nt][i] = 0.f;

    auto load_tiles = [&](int k0, int buf) {
        float* Ab = As + buf * TBM * APITCH;
        float* Wb = Ws + buf * TBK * WPITCH;
        #pragma unroll
        for (int i = 0; i < 4; i++) {
            int slot = tid + i * 256;
            int r  = slot >> 3;
            int c4 = (slot & 7) * 4;
            int gm = row0 + r;
            const float* src = A + (size_t)gm * K + k0 + c4;
            cp_async16(&Ab[r * APITCH + c4], src, (gm < M) ? 16 : 0);
        }
        #pragma unroll
        for (int i = 0; i < 4; i++) {
            int slot = tid + i * 256;
            int kr = slot >> 5;
            int nc = (slot & 31) * 4;
            const float* src = W + (size_t)(k0 + kr) * N + col0 + nc;
            cp_async16(&Wb[kr * WPITCH + nc], src, 16);
        }
        cp_commit();
    };

    int T = K / TBK;
    load_tiles(0, 0);

    for (int t = 0; t < T; t++) {
        int buf = t & 1;
        if (t + 1 < T) {
            load_tiles((t + 1) * TBK, (t + 1) & 1);
            asm volatile("cp.async.wait_group 1;");
        } else {
            asm volatile("cp.async.wait_group 0;");
        }
        __syncthreads();

        const float* Ab = As + buf * TBM * APITCH;
        const float* Wb = Ws + buf * TBK * WPITCH;
        #pragma unroll
        for (int ks = 0; ks < 4; ks++) {
            int kk = ks * 8;
            uint32_t af[4][4];
            #pragma unroll
            for (int mt = 0; mt < 4; mt++) {
                int m0 = wm + mt * 16;
                af[mt][0] = __float_as_uint(Ab[(m0 + g    ) * APITCH + kk + tig    ]);
                af[mt][1] = __float_as_uint(Ab[(m0 + g + 8) * APITCH + kk + tig    ]);
                af[mt][2] = __float_as_uint(Ab[(m0 + g    ) * APITCH + kk + tig + 4]);
                af[mt][3] = __float_as_uint(Ab[(m0 + g + 8) * APITCH + kk + tig + 4]);
            }
            #pragma unroll
            for (int nt = 0; nt < 4; nt++) {
                int n0 = wn + nt * 8;
                uint32_t b0 = __float_as_uint(Wb[(kk + tig    ) * WPITCH + n0 + g]);
                uint32_t b1 = __float_as_uint(Wb[(kk + tig + 4) * WPITCH + n0 + g]);
                #pragma unroll
                for (int mt = 0; mt < 4; mt++)
                    mma_tf32(acc[mt][nt], af[mt], b0, b1);
            }
        }
        __syncthreads();
    }

    #pragma unroll
    for (int mt = 0; mt < 4; mt++) {
        #pragma unroll
        for (int nt = 0; nt < 4; nt++) {
            int gn = col0 + wn + nt * 8 + tig * 2;
            #pragma unroll
            for (int half = 0; half < 2; half++) {
                int gm = row0 + wm + mt * 16 + g + half * 8;
                if (gm >= M) continue;
                #pragma unroll
                for (int cc = 0; cc < 2; cc++) {
                    float v = acc[mt][nt][half * 2 + cc] + bias[gn + cc];
                    if (mode == 1) {
                        v = 0.5f * v * (1.0f + erff(v * 0.70710678118654752f));
                        v = rnd_tf32(v);   // feeds fc2 GEMM A input
                    }
                    size_t off = (size_t)gm * N + gn + cc;
                    if (mode == 2) C[off] += v;
                    else C[off] = v;
                }
            }
        }
    }
}

// ---------------- LayerNorm over 768; output tf32-rounded (GEMM A input) --------
__global__ void ln_kernel(const float* __restrict__ in, float* __restrict__ out,
                          const float* __restrict__ w, const float* __restrict__ b,
                          long long in_stride, long long out_stride)
{
    __shared__ float red[8];
    const float* x = in + (long long)blockIdx.x * in_stride;
    float* y = out + (long long)blockIdx.x * out_stride;
    int t = threadIdx.x;
    float v0 = x[t], v1 = x[t + 256], v2 = x[t + 512];
    float mean = block_sum256(v0 + v1 + v2, red) * (1.f / 768.f);
    float d0 = v0 - mean, d1 = v1 - mean, d2 = v2 - mean;
    float var = block_sum256(d0 * d0 + d1 * d1 + d2 * d2, red) * (1.f / 768.f);
    float rstd = rsqrtf(var + 1e-6f);
    y[t]       = rnd_tf32(d0 * rstd * w[t]       + b[t]);
    y[t + 256] = rnd_tf32(d1 * rstd * w[t + 256] + b[t + 256]);
    y[t + 512] = rnd_tf32(d2 * rstd * w[t + 512] + b[t + 512]);
}

// ---------------- attention (coalesced, smem-tiled, P materialized) ----------------
#define SPAD 68

__global__ void __launch_bounds__(256) score_kernel(const float* __restrict__ qkv, int S)
{
    __shared__ float Qs[32][SPAD];
    __shared__ float KsT[64][SPAD];
    int q0 = blockIdx.x * 32, h = blockIdx.y, b = blockIdx.z;
    int tid = threadIdx.x;
    int q = tid >> 3, kg = tid & 7;
    const float* base = qkv + (size_t)b * S * (3 * DMODEL) + h * HDIM;
    float* prow = g_p + (((size_t)b * NHEAD + h) * PSTRIDE) * PSTRIDE;

    #pragma unroll
    for (int i = 0; i < 2; i++) {
        int slot = tid + i * 256;
        int r = slot >> 4, c4 = (slot & 15) * 4;
        int gq = q0 + r;
        float4 v = make_float4(0.f, 0.f, 0.f, 0.f);
        if (gq < S) v = *reinterpret_cast<const float4*>(&base[(size_t)gq * (3 * DMODEL) + c4]);
        *reinterpret_cast<float4*>(&Qs[r][c4]) = v;
    }

    int ntile = (S + 63) >> 6;
    for (int kt = 0; kt < ntile; kt++) {
        int k0 = kt * 64;
        #pragma unroll
        for (int i = 0; i < 4; i++) {
            int slot = tid + i * 256;
            int r = slot >> 4, c4 = (slot & 15) * 4;
            int gk = k0 + r;
            float4 v = make_float4(0.f, 0.f, 0.f, 0.f);
            if (gk < S) v = *reinterpret_cast<const float4*>(&base[(size_t)gk * (3 * DMODEL) + DMODEL + c4]);
            KsT[c4 + 0][r] = v.x;
            KsT[c4 + 1][r] = v.y;
            KsT[c4 + 2][r] = v.z;
            KsT[c4 + 3][r] = v.w;
        }
        __syncthreads();

        float acc[8];
        #pragma unroll
        for (int j = 0; j < 8; j++) acc[j] = 0.f;
        #pragma unroll
        for (int d = 0; d < HDIM; d++) {
            float qa = Qs[q][d];
            float4 kv0 = *reinterpret_cast<const float4*>(&KsT[d][kg * 8]);
            float4 kv1 = *reinterpret_cast<const float4*>(&KsT[d][kg * 8 + 4]);
            acc[0] += qa * kv0.x; acc[1] += qa * kv0.y;
            acc[2] += qa * kv0.z; acc[3] += qa * kv0.w;
            acc[4] += qa * kv1.x; acc[5] += qa * kv1.y;
            acc[6] += qa * kv1.z; acc[7] += qa * kv1.w;
        }
        int gq = q0 + q;
        if (gq < S) {
            float* pw = prow + (size_t)gq * PSTRIDE + k0 + kg * 8;
            #pragma unroll
            for (int j = 0; j < 8; j++) {
                int gk = k0 + kg * 8 + j;
                if (gk < S) pw[j] = acc[j] * 0.125f;
            }
        }
        __syncthreads();
    }
}

__global__ void softmax_kernel(int S)
{
    __shared__ float red[8];
    int q = blockIdx.x, h = blockIdx.y, b = blockIdx.z;
    float* prow = g_p + ((((size_t)b * NHEAD + h) * PSTRIDE) + q) * PSTRIDE;
    int t = threadIdx.x;
    float v = (t < S) ? prow[t] : -1e30f;
    float mx = block_max256(v, red);
    float e = (t < S) ? expf(v - mx) : 0.f;
    float sum = block_sum256(e, red);
    if (t < S) prow[t] = e / sum;
}

__global__ void __launch_bounds__(256) pv_kernel(const float* __restrict__ qkv,
                                                 float* __restrict__ o, int S)
{
    __shared__ float Ps[32][SPAD];
    __shared__ float Vs[64][SPAD];
    int q0 = blockIdx.x * 32, h = blockIdx.y, b = blockIdx.z;
    int tid = threadIdx.x;
    int q = tid >> 3, dg = tid & 7;
    const float* vbase = qkv + (size_t)b * S * (3 * DMODEL) + 2 * DMODEL + h * HDIM;
    const float* prow = g_p + (((size_t)b * NHEAD + h) * PSTRIDE) * PSTRIDE;

    float acc[8];
    #pragma unroll
    for (int j = 0; j < 8; j++) acc[j] = 0.f;

    int ntile = (S + 63) >> 6;
    for (int kt = 0; kt < ntile; kt++) {
        int k0 = kt * 64;
        #pragma unroll
        for (int i = 0; i < 2; i++) {
            int slot = tid + i * 256;
            int r = slot >> 4, c4 = (slot & 15) * 4;
            int gq = q0 + r;
            float4 v = make_float4(0.f, 0.f, 0.f, 0.f);
            if (gq < S) {
                #pragma unroll
                for (int c = 0; c < 4; c++) {
                    int gk = k0 + c4 + c;
                    ((float*)&v)[c] = (gk < S) ? prow[(size_t)gq * PSTRIDE + gk] : 0.f;
                }
            }
            *reinterpret_cast<float4*>(&Ps[r][c4]) = v;
        }
        #pragma unroll
        for (int i = 0; i < 4; i++) {
            int slot = tid + i * 256;
            int r = slot >> 4, c4 = (slot & 15) * 4;
            int gk = k0 + r;
            float4 v = make_float4(0.f, 0.f, 0.f, 0.f);
            if (gk < S) v = *reinterpret_cast<const float4*>(&vbase[(size_t)gk * (3 * DMODEL) + c4]);
            *reinterpret_cast<float4*>(&Vs[r][c4]) = v;
        }
        __syncthreads();

        #pragma unroll
        for (int k = 0; k < 64; k++) {
            float p = Ps[q][k];
            float4 v0 = *reinterpret_cast<const float4*>(&Vs[k][dg * 8]);
            float4 v1 = *reinterpret_cast<const float4*>(&Vs[k][dg * 8 + 4]);
            acc[0] += p * v0.x; acc[1] += p * v0.y;
            acc[2] += p * v0.z; acc[3] += p * v0.w;
            acc[4] += p * v1.x; acc[5] += p * v1.y;
            acc[6] += p * v1.z; acc[7] += p * v1.w;
        }
        __syncthreads();
    }

    int gq = q0 + q;
    if (gq < S) {
        float* ow = o + ((size_t)(b * S + gq)) * DMODEL + h * HDIM + dg * 8;
        #pragma unroll
        for (int j = 0; j < 8; j++) ow[j] = rnd_tf32(acc[j]);  // feeds proj GEMM
    }
}

// ---------------- patchify + embedding ----------------
__global__ void patchify_kernel(const float* __restrict__ in)
{
    size_t i = (size_t)blockIdx.x * 256 + threadIdx.x;
    if (i >= (size_t)BATCH * 196 * DMODEL) return;
    int v = (int)(i % DMODEL);
    size_t t = i / DMODEL;
    int p = (int)(t % 196);
    int b = (int)(t / 196);
    int c = v >> 8;
    int py = (v & 255) >> 4;
    int px = v & 15;
    int gy = p / 14, gx = p % 14;
    g_mlp[i] = rnd_tf32(in[(((size_t)b * 3 + c) * 224 + gy * 16 + py) * 224 + gx * 16 + px]);
}

__global__ void embed_kernel(const float* __restrict__ cls, const float* __restrict__ pos)
{
    size_t i = (size_t)blockIdx.x * 256 + threadIdx.x;
    if (i >= (size_t)BATCH * S1 * DMODEL) return;
    int d = (int)(i % DMODEL);
    size_t t = i / DMODEL;
    int s = (int)(t % S1);
    int b = (int)(t / S1);
    float v;
    if (s == 0) v = cls[d] + pos[d];
    else        v = g_o[((size_t)b * 196 + (s - 1)) * DMODEL + d] + pos[(size_t)s * DMODEL + d];
    g_x[i] = v;
    g_x0[i] = v;
}

// ---------------- routing ----------------
__global__ void pool_stats_kernel(const float* __restrict__ var)
{
    __shared__ float red[8];
    int p = blockIdx.x;
    const float* v = var + (size_t)p * DMODEL * DMODEL;
    float s = 0.f;
    for (int i = threadIdx.x; i < DMODEL * DMODEL; i += 256) { float t = v[i]; s += t * t; }
    float tot = block_sum256(s, red);
    if (threadIdx.x == 0) g_lognorm[p] = 0.25f * logf(tot);
}

__global__ void logwn_kernel(const float* __restrict__ freq)
{
    float m = freq[0];
    for (int i = 1; i < POOL; i++) m = fmaxf(m, freq[i]);
    float w[POOL]; float ss = 0.f;
    for (int i = 0; i < POOL; i++) { w[i] = m - freq[i]; ss += w[i] * w[i]; }
    float nz = fmaxf(sqrtf(ss), 1e-12f);
    for (int i = 0; i < POOL; i++) g_logwn[i] = logf(fmaxf(w[i] / nz, 1e-30f));
}

__global__ void quad_kernel(const float* __restrict__ keys, const float* __restrict__ inv_var)
{
    __shared__ float diff[DMODEL];
    __shared__ float red[8];
    int b = blockIdx.x, p = blockIdx.y;
    for (int i = threadIdx.x; i < DMODEL; i += 256)
        diff[i] = g_feat[b * DMODEL + i] - keys[p * DMODEL + i];
    __syncthreads();
    const float* M = inv_var + (size_t)p * DMODEL * DMODEL;
    float acc = 0.f;
    #pragma unroll
    for (int ei = 0; ei < 3; ei++) {
        int e = threadIdx.x + ei * 256;
        float inner = 0.f;
        for (int d = 0; d < DMODEL; d++)
            inner += diff[d] * M[(size_t)d * DMODEL + e];
        acc += inner * diff[e];
    }
    float quad = block_sum256(acc, red);
    if (threadIdx.x == 0)
        g_score[b * POOL + p] = -0.5f * quad + g_lognorm[p] + g_logwn[p];
}

__global__ void topk_kernel()
{
    int b = threadIdx.x;
    if (b >= BATCH) return;
    float s[POOL]; bool used[POOL];
    for (int p = 0; p < POOL; p++) { s[p] = g_score[b * POOL + p]; used[p] = false; }
    for (int i = 0; i < SEL; i++) {
        int best = 0; float bv = 3.0e38f;
        for (int p = 0; p < POOL; p++)
            if (!used[p] && s[p] < bv) { bv = s[p]; best = p; }
        used[best] = true;
        g_topk[b * SEL + i] = best;
    }
}

__global__ void build_sx_kernel(const float* __restrict__ prompts, const float* __restrict__ pos)
{
    size_t i = (size_t)blockIdx.x * 256 + threadIdx.x;
    if (i >= (size_t)BATCH * SMAX * DMODEL) return;
    int d = (int)(i % DMODEL);
    size_t t = i / DMODEL;
    int s = (int)(t % SMAX);
    int b = (int)(t / SMAX);
    float v;
    if (s == 0) {
        v = g_x0[(size_t)b * S1 * DMODEL + d];
    } else if (s <= SEL * PLEN) {
        int idx = s - 1;
        int pi = idx / PLEN, j = idx % PLEN;
        int pool = g_topk[b * SEL + pi];
        v = prompts[((size_t)pool * PLEN + j) * DMODEL + d] + pos[d];
    } else {
        v = g_x0[((size_t)b * S1 + (s - SEL * PLEN)) * DMODEL + d];
    }
    g_x[i] = v;
}

// ---------------- epilogue ----------------
__global__ void feat_kernel()
{
    int i = blockIdx.x * 256 + threadIdx.x;
    if (i >= BATCH * DMODEL) return;
    int b = i / DMODEL, d = i % DMODEL;
    float s = 0.f;
    for (int t = 1; t <= SEL * PLEN; t++)
        s += g_h[((size_t)b * SMAX + t) * DMODEL + d];
    g_feat[i] = s * (1.f / (SEL * PLEN));
}

__global__ void head_kernel(const float* __restrict__ hw, const float* __restrict__ hb,
                            float* __restrict__ out)
{
    int i = blockIdx.x * 256 + threadIdx.x;
    if (i >= BATCH * NCLS) return;
    int b = i / NCLS, n = i % NCLS;
    float acc = hb[n];
    for (int k = 0; k < DMODEL; k++) acc += g_feat[b * DMODEL + k] * hw[k * NCLS + n];
    out[i] = acc;
}

// ---------------- host orchestration ----------------
static void run_vit(int S, int M,
    const float* ln1w, const float* ln1b, const float* qkvw, const float* qkvb,
    const float* pw, const float* pb, const float* ln2w, const float* ln2b,
    const float* f1w, const float* f1b, const float* f2w, const float* f2b,
    float* px, float* ph, float* pqkv, float* po, float* pmlp)
{
    int gy = (M + TBM - 1) / TBM;
    int qt = (S + 31) / 32;
    for (int l = 0; l < NLAYER; l++) {
        ln_kernel<<<M, 256>>>(px, ph, ln1w + (size_t)l * DMODEL, ln1b + (size_t)l * DMODEL, DMODEL, DMODEL);
        tc_gemm_kernel<<<dim3(3 * DMODEL / TBN, gy), 256, GEMM_SMEM>>>(ph, qkvw + (size_t)l * DMODEL * 3 * DMODEL,
                                                            qkvb + (size_t)l * 3 * DMODEL, pqkv, M, 3 * DMODEL, DMODEL, 0);
        score_kernel<<<dim3(qt, NHEAD, BATCH), 256>>>(pqkv, S);
        softmax_kernel<<<dim3(S, NHEAD, BATCH), 256>>>(S);
        pv_kernel<<<dim3(qt, NHEAD, BATCH), 256>>>(pqkv, po, S);
        tc_gemm_kernel<<<dim3(DMODEL / TBN, gy), 256, GEMM_SMEM>>>(po, pw + (size_t)l * DMODEL * DMODEL,
                                                        pb + (size_t)l * DMODEL, px, M, DMODEL, DMODEL, 2);
        ln_kernel<<<M, 256>>>(px, ph, ln2w + (size_t)l * DMODEL, ln2b + (size_t)l * DMODEL, DMODEL, DMODEL);
        tc_gemm_kernel<<<dim3(MLPD / TBN, gy), 256, GEMM_SMEM>>>(ph, f1w + (size_t)l * DMODEL * MLPD,
                                                      f1b + (size_t)l * MLPD, pmlp, M, MLPD, DMODEL, 1);
        tc_gemm_kernel<<<dim3(DMODEL / TBN, gy), 256, GEMM_SMEM>>>(pmlp, f2w + (size_t)l * MLPD * DMODEL,
                                                        f2b + (size_t)l * DMODEL, px, M, DMODEL, MLPD, 2);
    }
}

extern "C" void kernel_launch(void* const* d_in, const int* in_sizes, int n_in,
                              void* d_out, int out_size)
{
    const float* inputs    = (const float*)d_in[0];
    const float* patch_w   = (const float*)d_in[1];
    const float* patch_b   = (const float*)d_in[2];
    const float* cls_token = (const float*)d_in[3];
    const float* pos_embed = (const float*)d_in[4];
    const float* ln1_w = (const float*)d_in[5];
    const float* ln1_b = (const float*)d_in[6];
    const float* qkv_w = (const float*)d_in[7];
    const float* qkv_b = (const float*)d_in[8];
    const float* proj_w = (const float*)d_in[9];
    const float* proj_b = (const float*)d_in[10];
    const float* ln2_w = (const float*)d_in[11];
    const float* ln2_b = (const float*)d_in[12];
    const float* fc1_w = (const float*)d_in[13];
    const float* fc1_b = (const float*)d_in[14];
    const float* fc2_w = (const float*)d_in[15];
    const float* fc2_b = (const float*)d_in[16];
    const float* norm_w = (const float*)d_in[17];
    const float* norm_b = (const float*)d_in[18];
    const float* head_w = (const float*)d_in[19];
    const float* head_b = (const float*)d_in[20];
    const float* key_pool = (const float*)d_in[21];
    const float* frequency = (const float*)d_in[22];
    const float* prompts = (const float*)d_in[23];
    const float* variance = (const float*)d_in[24];
    const float* inv_variance = (const float*)d_in[25];

    static bool attr_set = false;
    if (!attr_set) {
        cudaFuncSetAttribute(tc_gemm_kernel, cudaFuncAttributeMaxDynamicSharedMemorySize, GEMM_SMEM);
        attr_set = true;
    }

    float *px, *ph, *pqkv, *po, *pmlp, *pfeat;
    float *pwq, *pwp, *pw1, *pw2, *pwpc;
    cudaGetSymbolAddress((void**)&px,   g_x);
    cudaGetSymbolAddress((void**)&ph,   g_h);
    cudaGetSymbolAddress((void**)&pqkv, g_qkv);
    cudaGetSymbolAddress((void**)&po,   g_o);
    cudaGetSymbolAddress((void**)&pmlp, g_mlp);
    cudaGetSymbolAddress((void**)&pfeat, g_feat);
    cudaGetSymbolAddress((void**)&pwq,  g_wq);
    cudaGetSymbolAddress((void**)&pwp,  g_wp);
    cudaGetSymbolAddress((void**)&pw1,  g_w1);
    cudaGetSymbolAddress((void**)&pw2,  g_w2);
    cudaGetSymbolAddress((void**)&pwpc, g_wpc);

    // 0) pre-round weights to tf32 (once per launch; ~0.2 ms)
    {
        long long nq = (long long)NLAYER * DMODEL * 3 * DMODEL;
        long long np = (long long)NLAYER * DMODEL * DMODEL;
        long long n1 = (long long)NLAYER * DMODEL * MLPD;
        long long npc = (long long)DMODEL * DMODEL;
        round_tf32_kernel<<<(int)((nq / 4 + 255) / 256), 256>>>(qkv_w, pwq, nq);
        round_tf32_kernel<<<(int)((np / 4 + 255) / 256), 256>>>(proj_w, pwp, np);
        round_tf32_kernel<<<(int)((n1 / 4 + 255) / 256), 256>>>(fc1_w, pw1, n1);
        round_tf32_kernel<<<(int)((n1 / 4 + 255) / 256), 256>>>(fc2_w, pw2, n1);
        round_tf32_kernel<<<(int)((npc / 4 + 255) / 256), 256>>>(patch_w, pwpc, npc);
    }

    // 1) patch embed
    patchify_kernel<<<(BATCH * 196 * DMODEL + 255) / 256, 256>>>(inputs);
    tc_gemm_kernel<<<dim3(DMODEL / TBN, (BATCH * 196 + TBM - 1) / TBM), 256, GEMM_SMEM>>>(
        pmlp, pwpc, patch_b, po, BATCH * 196, DMODEL, DMODEL, 0);
    embed_kernel<<<(BATCH * S1 * DMODEL + 255) / 256, 256>>>(cls_token, pos_embed);

    // 2) first ViT pass (S=197)
    run_vit(S1, BATCH * S1, ln1_w, ln1_b, pwq, qkv_b, pwp, proj_b,
            ln2_w, ln2_b, pw1, fc1_b, pw2, fc2_b, px, ph, pqkv, po, pmlp);

    // 3) routing
    ln_kernel<<<BATCH, 256>>>(px, pfeat, norm_w, norm_b, (long long)S1 * DMODEL, DMODEL);
    pool_stats_kernel<<<POOL, 256>>>(variance);
    logwn_kernel<<<1, 1>>>(frequency);
    quad_kernel<<<dim3(BATCH, POOL), 256>>>(key_pool, inv_variance);
    topk_kernel<<<1, 32>>>();

    // 4) splice prompts (S=222)
    build_sx_kernel<<<(BATCH * SMAX * DMODEL + 255) / 256, 256>>>(prompts, pos_embed);

    // 5) second ViT pass (S=222)
    run_vit(SMAX, BATCH * SMAX, ln1_w, ln1_b, pwq, qkv_b, pwp, proj_b,
            ln2_w, ln2_b, pw1, fc1_b, pw2, fc2_b, px, ph, pqkv, po, pmlp);

    // 6) final LN, mean over prompt tokens, head
    ln_kernel<<<BATCH * SMAX, 256>>>(px, ph, norm_w, norm_b, DMODEL, DMODEL);
    feat_kernel<<<(BATCH * DMODEL + 255) / 256, 256>>>();
    head_kernel<<<(BATCH * NCLS + 255) / 256, 256>>>(head_w, head_b, (float*)d_out);
}

// round 9
// speedup vs baseline: 1.5823x; 1.5823x over previous
#include <cuda_runtime.h>
#include <cstdint>

#define BATCH  32
#define SMAX   222
#define S1     197
#define DMODEL 768
#define NLAYER 12
#define NHEAD  12
#define HDIM   64
#define MLPD   3072
#define POOL   10
#define SEL    5
#define PLEN   5
#define NCLS   100
#define PSTRIDE 224

// ---------------- scratch (static device allocations; harness-legal) ----------------
__device__ float g_x   [BATCH * SMAX * DMODEL];
__device__ float g_x0  [BATCH * S1   * DMODEL];
__device__ float g_h   [BATCH * SMAX * DMODEL];
__device__ float g_qkv [BATCH * SMAX * 3 * DMODEL];
__device__ float g_o   [BATCH * SMAX * DMODEL];
__device__ float g_mlp [BATCH * SMAX * MLPD];
__device__ float g_p   [BATCH * NHEAD * PSTRIDE * PSTRIDE];
__device__ float g_feat[BATCH * DMODEL];
__device__ float g_score[BATCH * POOL];
__device__ float g_lognorm[POOL];
__device__ float g_logwn[POOL];
__device__ int   g_topk[BATCH * SEL];

// tf32-pre-rounded weight copies (converted once per launch)
__device__ float g_wq [NLAYER * DMODEL * 3 * DMODEL];
__device__ float g_wp [NLAYER * DMODEL * DMODEL];
__device__ float g_w1 [NLAYER * DMODEL * MLPD];
__device__ float g_w2 [NLAYER * MLPD * DMODEL];
__device__ float g_wpc[DMODEL * DMODEL];

// ---------------- reductions (blockDim == 256 assumed) ----------------
__device__ __forceinline__ float block_sum256(float v, float* red) {
    int lane = threadIdx.x & 31, wid = threadIdx.x >> 5;
    #pragma unroll
    for (int o = 16; o; o >>= 1) v += __shfl_xor_sync(0xffffffffu, v, o);
    if (lane == 0) red[wid] = v;
    __syncthreads();
    float r = (lane < 8) ? red[lane] : 0.f;
    #pragma unroll
    for (int o = 4; o; o >>= 1) r += __shfl_xor_sync(0xffffffffu, r, o);
    r = __shfl_sync(0xffffffffu, r, 0);
    __syncthreads();
    return r;
}

__device__ __forceinline__ float block_max256(float v, float* red) {
    int lane = threadIdx.x & 31, wid = threadIdx.x >> 5;
    #pragma unroll
    for (int o = 16; o; o >>= 1) v = fmaxf(v, __shfl_xor_sync(0xffffffffu, v, o));
    if (lane == 0) red[wid] = v;
    __syncthreads();
    float r = (lane < 8) ? red[lane] : -1e30f;
    #pragma unroll
    for (int o = 4; o; o >>= 1) r = fmaxf(r, __shfl_xor_sync(0xffffffffu, r, o));
    r = __shfl_sync(0xffffffffu, r, 0);
    __syncthreads();
    return r;
}

// ---------------- tf32 helpers ----------------
__device__ __forceinline__ uint32_t f2tf32(float x) {
    uint32_t u;
    asm("cvt.rna.tf32.f32 %0, %1;" : "=r"(u) : "f"(x));
    return u;
}
__device__ __forceinline__ float rnd_tf32(float x) { return __uint_as_float(f2tf32(x)); }

__device__ __forceinline__ void mma_tf32(float* c, const uint32_t* a, uint32_t b0, uint32_t b1) {
    asm volatile(
        "mma.sync.aligned.m16n8k8.row.col.f32.tf32.tf32.f32 "
        "{%0,%1,%2,%3}, {%4,%5,%6,%7}, {%8,%9}, {%0,%1,%2,%3};"
        : "+f"(c[0]), "+f"(c[1]), "+f"(c[2]), "+f"(c[3])
        : "r"(a[0]), "r"(a[1]), "r"(a[2]), "r"(a[3]), "r"(b0), "r"(b1));
}

__device__ __forceinline__ void cp_async16(void* smem_dst, const void* gsrc, int src_bytes) {
    unsigned sa = (unsigned)__cvta_generic_to_shared(smem_dst);
    asm volatile("cp.async.cg.shared.global [%0], [%1], 16, %2;"
                 :: "r"(sa), "l"(gsrc), "r"(src_bytes));
}
__device__ __forceinline__ void cp_commit() {
    asm volatile("cp.async.commit_group;");
}

// weight pre-round: dst = tf32(src), vectorized
__global__ void round_tf32_kernel(const float* __restrict__ src, float* __restrict__ dst, long long n)
{
    long long i = ((long long)blockIdx.x * 256 + threadIdx.x) * 4;
    if (i + 3 < n) {
        float4 v = *reinterpret_cast<const float4*>(&src[i]);
        v.x = rnd_tf32(v.x); v.y = rnd_tf32(v.y); v.z = rnd_tf32(v.z); v.w = rnd_tf32(v.w);
        *reinterpret_cast<float4*>(&dst[i]) = v;
    } else {
        for (; i < n; i++) dst[i] = rnd_tf32(src[i]);
    }
}

// ---------------- pipelined tf32 tensor-core GEMM ----------------
// Inputs A and W are ALREADY tf32-rounded. C = A@W + bias.
// mode 0 = store, 1 = GELU store (tf32-rounded), 2 = add into C
// NOTE: no minBlocksPerMultiprocessor — forcing 2 CTAs/SM caps regs at 128 and
// spills the accumulators (round-8 regression, 36.7 -> 56.2 ms).
#define TBM 128
#define TBN 128
#define TBK 32
#define APITCH 36
#define WPITCH 136
#define GEMM_SMEM ((2 * TBM * APITCH + 2 * TBK * WPITCH) * 4)

__global__ void __launch_bounds__(256) tc_gemm_kernel(
    const float* __restrict__ A, const float* __restrict__ W,
    const float* __restrict__ bias, float* __restrict__ C,
    int M, int N, int K, int mode)
{
    extern __shared__ float smem[];
    float* As = smem;                       // [2][TBM][APITCH]
    float* Ws = smem + 2 * TBM * APITCH;    // [2][TBK][WPITCH]

    int tid  = threadIdx.x;
    int warp = tid >> 5, lane = tid & 31;
    int g = lane >> 2, tig = lane & 3;
    int wm = (warp & 1) * 64;
    int wn = (warp >> 1) * 32;
    int row0 = blockIdx.y * TBM;
    int col0 = blockIdx.x * TBN;

    float acc[4][4][4];
    #pragma unroll
    for (int mt = 0; mt < 4; mt++)
        #pragma unroll
        for (int nt = 0; nt < 4; nt++)
            #pragma unroll
            for (int i = 0; i < 4; i++) acc[mt][nt][i] = 0.f;

    auto load_tiles = [&](int k0, int buf) {
        float* Ab = As + buf * TBM * APITCH;
        float* Wb = Ws + buf * TBK * WPITCH;
        #pragma unroll
        for (int i = 0; i < 4; i++) {
            int slot = tid + i * 256;
            int r  = slot >> 3;
            int c4 = (slot & 7) * 4;
            int gm = row0 + r;
            const float* src = A + (size_t)gm * K + k0 + c4;
            cp_async16(&Ab[r * APITCH + c4], src, (gm < M) ? 16 : 0);
        }
        #pragma unroll
        for (int i = 0; i < 4; i++) {
            int slot = tid + i * 256;
            int kr = slot >> 5;
            int nc = (slot & 31) * 4;
            const float* src = W + (size_t)(k0 + kr) * N + col0 + nc;
            cp_async16(&Wb[kr * WPITCH + nc], src, 16);
        }
        cp_commit();
    };

    int T = K / TBK;
    load_tiles(0, 0);

    for (int t = 0; t < T; t++) {
        int buf = t & 1;
        if (t + 1 < T) {
            load_tiles((t + 1) * TBK, (t + 1) & 1);
            asm volatile("cp.async.wait_group 1;");
        } else {
            asm volatile("cp.async.wait_group 0;");
        }
        __syncthreads();

        const float* Ab = As + buf * TBM * APITCH;
        const float* Wb = Ws + buf * TBK * WPITCH;
        #pragma unroll
        for (int ks = 0; ks < 4; ks++) {
            int kk = ks * 8;
            uint32_t af[4][4];
            #pragma unroll
            for (int mt = 0; mt < 4; mt++) {
                int m0 = wm + mt * 16;
                af[mt][0] = __float_as_uint(Ab[(m0 + g    ) * APITCH + kk + tig    ]);
                af[mt][1] = __float_as_uint(Ab[(m0 + g + 8) * APITCH + kk + tig    ]);
                af[mt][2] = __float_as_uint(Ab[(m0 + g    ) * APITCH + kk + tig + 4]);
                af[mt][3] = __float_as_uint(Ab[(m0 + g + 8) * APITCH + kk + tig + 4]);
            }
            #pragma unroll
            for (int nt = 0; nt < 4; nt++) {
                int n0 = wn + nt * 8;
                uint32_t b0 = __float_as_uint(Wb[(kk + tig    ) * WPITCH + n0 + g]);
                uint32_t b1 = __float_as_uint(Wb[(kk + tig + 4) * WPITCH + n0 + g]);
                #pragma unroll
                for (int mt = 0; mt < 4; mt++)
                    mma_tf32(acc[mt][nt], af[mt], b0, b1);
            }
        }
        __syncthreads();
    }

    #pragma unroll
    for (int mt = 0; mt < 4; mt++) {
        #pragma unroll
        for (int nt = 0; nt < 4; nt++) {
            int gn = col0 + wn + nt * 8 + tig * 2;
            #pragma unroll
            for (int half = 0; half < 2; half++) {
                int gm = row0 + wm + mt * 16 + g + half * 8;
                if (gm >= M) continue;
                #pragma unroll
                for (int cc = 0; cc < 2; cc++) {
                    float v = acc[mt][nt][half * 2 + cc] + bias[gn + cc];
                    if (mode == 1) {
                        v = 0.5f * v * (1.0f + erff(v * 0.70710678118654752f));
                        v = rnd_tf32(v);   // feeds fc2 GEMM A input
                    }
                    size_t off = (size_t)gm * N + gn + cc;
                    if (mode == 2) C[off] += v;
                    else C[off] = v;
                }
            }
        }
    }
}

// ---------------- LayerNorm over 768; output tf32-rounded (GEMM A input) --------
__global__ void ln_kernel(const float* __restrict__ in, float* __restrict__ out,
                          const float* __restrict__ w, const float* __restrict__ b,
                          long long in_stride, long long out_stride)
{
    __shared__ float red[8];
    const float* x = in + (long long)blockIdx.x * in_stride;
    float* y = out + (long long)blockIdx.x * out_stride;
    int t = threadIdx.x;
    float v0 = x[t], v1 = x[t + 256], v2 = x[t + 512];
    float mean = block_sum256(v0 + v1 + v2, red) * (1.f / 768.f);
    float d0 = v0 - mean, d1 = v1 - mean, d2 = v2 - mean;
    float var = block_sum256(d0 * d0 + d1 * d1 + d2 * d2, red) * (1.f / 768.f);
    float rstd = rsqrtf(var + 1e-6f);
    y[t]       = rnd_tf32(d0 * rstd * w[t]       + b[t]);
    y[t + 256] = rnd_tf32(d1 * rstd * w[t + 256] + b[t + 256]);
    y[t + 512] = rnd_tf32(d2 * rstd * w[t + 512] + b[t + 512]);
}

// ---------------- attention (coalesced, smem-tiled, P materialized) ----------------
#define SPAD 68

__global__ void __launch_bounds__(256) score_kernel(const float* __restrict__ qkv, int S)
{
    __shared__ float Qs[32][SPAD];
    __shared__ float KsT[64][SPAD];
    int q0 = blockIdx.x * 32, h = blockIdx.y, b = blockIdx.z;
    int tid = threadIdx.x;
    int q = tid >> 3, kg = tid & 7;
    const float* base = qkv + (size_t)b * S * (3 * DMODEL) + h * HDIM;
    float* prow = g_p + (((size_t)b * NHEAD + h) * PSTRIDE) * PSTRIDE;

    #pragma unroll
    for (int i = 0; i < 2; i++) {
        int slot = tid + i * 256;
        int r = slot >> 4, c4 = (slot & 15) * 4;
        int gq = q0 + r;
        float4 v = make_float4(0.f, 0.f, 0.f, 0.f);
        if (gq < S) v = *reinterpret_cast<const float4*>(&base[(size_t)gq * (3 * DMODEL) + c4]);
        *reinterpret_cast<float4*>(&Qs[r][c4]) = v;
    }

    int ntile = (S + 63) >> 6;
    for (int kt = 0; kt < ntile; kt++) {
        int k0 = kt * 64;
        #pragma unroll
        for (int i = 0; i < 4; i++) {
            int slot = tid + i * 256;
            int r = slot >> 4, c4 = (slot & 15) * 4;
            int gk = k0 + r;
            float4 v = make_float4(0.f, 0.f, 0.f, 0.f);
            if (gk < S) v = *reinterpret_cast<const float4*>(&base[(size_t)gk * (3 * DMODEL) + DMODEL + c4]);
            KsT[c4 + 0][r] = v.x;
            KsT[c4 + 1][r] = v.y;
            KsT[c4 + 2][r] = v.z;
            KsT[c4 + 3][r] = v.w;
        }
        __syncthreads();

        float acc[8];
        #pragma unroll
        for (int j = 0; j < 8; j++) acc[j] = 0.f;
        #pragma unroll
        for (int d = 0; d < HDIM; d++) {
            float qa = Qs[q][d];
            float4 kv0 = *reinterpret_cast<const float4*>(&KsT[d][kg * 8]);
            float4 kv1 = *reinterpret_cast<const float4*>(&KsT[d][kg * 8 + 4]);
            acc[0] += qa * kv0.x; acc[1] += qa * kv0.y;
            acc[2] += qa * kv0.z; acc[3] += qa * kv0.w;
            acc[4] += qa * kv1.x; acc[5] += qa * kv1.y;
            acc[6] += qa * kv1.z; acc[7] += qa * kv1.w;
        }
        int gq = q0 + q;
        if (gq < S) {
            float* pw = prow + (size_t)gq * PSTRIDE + k0 + kg * 8;
            #pragma unroll
            for (int j = 0; j < 8; j++) {
                int gk = k0 + kg * 8 + j;
                if (gk < S) pw[j] = acc[j] * 0.125f;
            }
        }
        __syncthreads();
    }
}

__global__ void softmax_kernel(int S)
{
    __shared__ float red[8];
    int q = blockIdx.x, h = blockIdx.y, b = blockIdx.z;
    float* prow = g_p + ((((size_t)b * NHEAD + h) * PSTRIDE) + q) * PSTRIDE;
    int t = threadIdx.x;
    float v = (t < S) ? prow[t] : -1e30f;
    float mx = block_max256(v, red);
    float e = (t < S) ? expf(v - mx) : 0.f;
    float sum = block_sum256(e, red);
    if (t < S) prow[t] = e / sum;
}

__global__ void __launch_bounds__(256) pv_kernel(const float* __restrict__ qkv,
                                                 float* __restrict__ o, int S)
{
    __shared__ float Ps[32][SPAD];
    __shared__ float Vs[64][SPAD];
    int q0 = blockIdx.x * 32, h = blockIdx.y, b = blockIdx.z;
    int tid = threadIdx.x;
    int q = tid >> 3, dg = tid & 7;
    const float* vbase = qkv + (size_t)b * S * (3 * DMODEL) + 2 * DMODEL + h * HDIM;
    const float* prow = g_p + (((size_t)b * NHEAD + h) * PSTRIDE) * PSTRIDE;

    float acc[8];
    #pragma unroll
    for (int j = 0; j < 8; j++) acc[j] = 0.f;

    int ntile = (S + 63) >> 6;
    for (int kt = 0; kt < ntile; kt++) {
        int k0 = kt * 64;
        #pragma unroll
        for (int i = 0; i < 2; i++) {
            int slot = tid + i * 256;
            int r = slot >> 4, c4 = (slot & 15) * 4;
            int gq = q0 + r;
            float4 v = make_float4(0.f, 0.f, 0.f, 0.f);
            if (gq < S) {
                #pragma unroll
                for (int c = 0; c < 4; c++) {
                    int gk = k0 + c4 + c;
                    ((float*)&v)[c] = (gk < S) ? prow[(size_t)gq * PSTRIDE + gk] : 0.f;
                }
            }
            *reinterpret_cast<float4*>(&Ps[r][c4]) = v;
        }
        #pragma unroll
        for (int i = 0; i < 4; i++) {
            int slot = tid + i * 256;
            int r = slot >> 4, c4 = (slot & 15) * 4;
            int gk = k0 + r;
            float4 v = make_float4(0.f, 0.f, 0.f, 0.f);
            if (gk < S) v = *reinterpret_cast<const float4*>(&vbase[(size_t)gk * (3 * DMODEL) + c4]);
            *reinterpret_cast<float4*>(&Vs[r][c4]) = v;
        }
        __syncthreads();

        #pragma unroll
        for (int k = 0; k < 64; k++) {
            float p = Ps[q][k];
            float4 v0 = *reinterpret_cast<const float4*>(&Vs[k][dg * 8]);
            float4 v1 = *reinterpret_cast<const float4*>(&Vs[k][dg * 8 + 4]);
            acc[0] += p * v0.x; acc[1] += p * v0.y;
            acc[2] += p * v0.z; acc[3] += p * v0.w;
            acc[4] += p * v1.x; acc[5] += p * v1.y;
            acc[6] += p * v1.z; acc[7] += p * v1.w;
        }
        __syncthreads();
    }

    int gq = q0 + q;
    if (gq < S) {
        float* ow = o + ((size_t)(b * S + gq)) * DMODEL + h * HDIM + dg * 8;
        #pragma unroll
        for (int j = 0; j < 8; j++) ow[j] = rnd_tf32(acc[j]);  // feeds proj GEMM
    }
}

// ---------------- patchify + embedding ----------------
__global__ void patchify_kernel(const float* __restrict__ in)
{
    size_t i = (size_t)blockIdx.x * 256 + threadIdx.x;
    if (i >= (size_t)BATCH * 196 * DMODEL) return;
    int v = (int)(i % DMODEL);
    size_t t = i / DMODEL;
    int p = (int)(t % 196);
    int b = (int)(t / 196);
    int c = v >> 8;
    int py = (v & 255) >> 4;
    int px = v & 15;
    int gy = p / 14, gx = p % 14;
    g_mlp[i] = rnd_tf32(in[(((size_t)b * 3 + c) * 224 + gy * 16 + py) * 224 + gx * 16 + px]);
}

__global__ void embed_kernel(const float* __restrict__ cls, const float* __restrict__ pos)
{
    size_t i = (size_t)blockIdx.x * 256 + threadIdx.x;
    if (i >= (size_t)BATCH * S1 * DMODEL) return;
    int d = (int)(i % DMODEL);
    size_t t = i / DMODEL;
    int s = (int)(t % S1);
    int b = (int)(t / S1);
    float v;
    if (s == 0) v = cls[d] + pos[d];
    else        v = g_o[((size_t)b * 196 + (s - 1)) * DMODEL + d] + pos[(size_t)s * DMODEL + d];
    g_x[i] = v;
    g_x0[i] = v;
}

// ---------------- routing ----------------
__global__ void pool_stats_kernel(const float* __restrict__ var)
{
    __shared__ float red[8];
    int p = blockIdx.x;
    const float* v = var + (size_t)p * DMODEL * DMODEL;
    float s = 0.f;
    for (int i = threadIdx.x; i < DMODEL * DMODEL; i += 256) { float t = v[i]; s += t * t; }
    float tot = block_sum256(s, red);
    if (threadIdx.x == 0) g_lognorm[p] = 0.25f * logf(tot);
}

__global__ void logwn_kernel(const float* __restrict__ freq)
{
    float m = freq[0];
    for (int i = 1; i < POOL; i++) m = fmaxf(m, freq[i]);
    float w[POOL]; float ss = 0.f;
    for (int i = 0; i < POOL; i++) { w[i] = m - freq[i]; ss += w[i] * w[i]; }
    float nz = fmaxf(sqrtf(ss), 1e-12f);
    for (int i = 0; i < POOL; i++) g_logwn[i] = logf(fmaxf(w[i] / nz, 1e-30f));
}

__global__ void quad_kernel(const float* __restrict__ keys, const float* __restrict__ inv_var)
{
    __shared__ float diff[DMODEL];
    __shared__ float red[8];
    int b = blockIdx.x, p = blockIdx.y;
    for (int i = threadIdx.x; i < DMODEL; i += 256)
        diff[i] = g_feat[b * DMODEL + i] - keys[p * DMODEL + i];
    __syncthreads();
    const float* M = inv_var + (size_t)p * DMODEL * DMODEL;
    float acc = 0.f;
    #pragma unroll
    for (int ei = 0; ei < 3; ei++) {
        int e = threadIdx.x + ei * 256;
        float inner = 0.f;
        for (int d = 0; d < DMODEL; d++)
            inner += diff[d] * M[(size_t)d * DMODEL + e];
        acc += inner * diff[e];
    }
    float quad = block_sum256(acc, red);
    if (threadIdx.x == 0)
        g_score[b * POOL + p] = -0.5f * quad + g_lognorm[p] + g_logwn[p];
}

__global__ void topk_kernel()
{
    int b = threadIdx.x;
    if (b >= BATCH) return;
    float s[POOL]; bool used[POOL];
    for (int p = 0; p < POOL; p++) { s[p] = g_score[b * POOL + p]; used[p] = false; }
    for (int i = 0; i < SEL; i++) {
        int best = 0; float bv = 3.0e38f;
        for (int p = 0; p < POOL; p++)
            if (!used[p] && s[p] < bv) { bv = s[p]; best = p; }
        used[best] = true;
        g_topk[b * SEL + i] = best;
    }
}

__global__ void build_sx_kernel(const float* __restrict__ prompts, const float* __restrict__ pos)
{
    size_t i = (size_t)blockIdx.x * 256 + threadIdx.x;
    if (i >= (size_t)BATCH * SMAX * DMODEL) return;
    int d = (int)(i % DMODEL);
    size_t t = i / DMODEL;
    int s = (int)(t % SMAX);
    int b = (int)(t / SMAX);
    float v;
    if (s == 0) {
        v = g_x0[(size_t)b * S1 * DMODEL + d];
    } else if (s <= SEL * PLEN) {
        int idx = s - 1;
        int pi = idx / PLEN, j = idx % PLEN;
        int pool = g_topk[b * SEL + pi];
        v = prompts[((size_t)pool * PLEN + j) * DMODEL + d] + pos[d];
    } else {
        v = g_x0[((size_t)b * S1 + (s - SEL * PLEN)) * DMODEL + d];
    }
    g_x[i] = v;
}

// ---------------- epilogue ----------------
__global__ void feat_kernel()
{
    int i = blockIdx.x * 256 + threadIdx.x;
    if (i >= BATCH * DMODEL) return;
    int b = i / DMODEL, d = i % DMODEL;
    float s = 0.f;
    for (int t = 1; t <= SEL * PLEN; t++)
        s += g_h[((size_t)b * SMAX + t) * DMODEL + d];
    g_feat[i] = s * (1.f / (SEL * PLEN));
}

__global__ void head_kernel(const float* __restrict__ hw, const float* __restrict__ hb,
                            float* __restrict__ out)
{
    int i = blockIdx.x * 256 + threadIdx.x;
    if (i >= BATCH * NCLS) return;
    int b = i / NCLS, n = i % NCLS;
    float acc = hb[n];
    for (int k = 0; k < DMODEL; k++) acc += g_feat[b * DMODEL + k] * hw[k * NCLS + n];
    out[i] = acc;
}

// ---------------- host orchestration ----------------
static void run_vit(int S, int M,
    const float* ln1w, const float* ln1b, const float* qkvw, const float* qkvb,
    const float* pw, const float* pb, const float* ln2w, const float* ln2b,
    const float* f1w, const float* f1b, const float* f2w, const float* f2b,
    float* px, float* ph, float* pqkv, float* po, float* pmlp)
{
    int gy = (M + TBM - 1) / TBM;
    int qt = (S + 31) / 32;
    for (int l = 0; l < NLAYER; l++) {
        ln_kernel<<<M, 256>>>(px, ph, ln1w + (size_t)l * DMODEL, ln1b + (size_t)l * DMODEL, DMODEL, DMODEL);
        tc_gemm_kernel<<<dim3(3 * DMODEL / TBN, gy), 256, GEMM_SMEM>>>(ph, qkvw + (size_t)l * DMODEL * 3 * DMODEL,
                                                            qkvb + (size_t)l * 3 * DMODEL, pqkv, M, 3 * DMODEL, DMODEL, 0);
        score_kernel<<<dim3(qt, NHEAD, BATCH), 256>>>(pqkv, S);
        softmax_kernel<<<dim3(S, NHEAD, BATCH), 256>>>(S);
        pv_kernel<<<dim3(qt, NHEAD, BATCH), 256>>>(pqkv, po, S);
        tc_gemm_kernel<<<dim3(DMODEL / TBN, gy), 256, GEMM_SMEM>>>(po, pw + (size_t)l * DMODEL * DMODEL,
                                                        pb + (size_t)l * DMODEL, px, M, DMODEL, DMODEL, 2);
        ln_kernel<<<M, 256>>>(px, ph, ln2w + (size_t)l * DMODEL, ln2b + (size_t)l * DMODEL, DMODEL, DMODEL);
        tc_gemm_kernel<<<dim3(MLPD / TBN, gy), 256, GEMM_SMEM>>>(ph, f1w + (size_t)l * DMODEL * MLPD,
                                                      f1b + (size_t)l * MLPD, pmlp, M, MLPD, DMODEL, 1);
        tc_gemm_kernel<<<dim3(DMODEL / TBN, gy), 256, GEMM_SMEM>>>(pmlp, f2w + (size_t)l * MLPD * DMODEL,
                                                        f2b + (size_t)l * DMODEL, px, M, DMODEL, MLPD, 2);
    }
}

extern "C" void kernel_launch(void* const* d_in, const int* in_sizes, int n_in,
                              void* d_out, int out_size)
{
    const float* inputs    = (const float*)d_in[0];
    const float* patch_w   = (const float*)d_in[1];
    const float* patch_b   = (const float*)d_in[2];
    const float* cls_token = (const float*)d_in[3];
    const float* pos_embed = (const float*)d_in[4];
    const float* ln1_w = (const float*)d_in[5];
    const float* ln1_b = (const float*)d_in[6];
    const float* qkv_w = (const float*)d_in[7];
    const float* qkv_b = (const float*)d_in[8];
    const float* proj_w = (const float*)d_in[9];
    const float* proj_b = (const float*)d_in[10];
    const float* ln2_w = (const float*)d_in[11];
    const float* ln2_b = (const float*)d_in[12];
    const float* fc1_w = (const float*)d_in[13];
    const float* fc1_b = (const float*)d_in[14];
    const float* fc2_w = (const float*)d_in[15];
    const float* fc2_b = (const float*)d_in[16];
    const float* norm_w = (const float*)d_in[17];
    const float* norm_b = (const float*)d_in[18];
    const float* head_w = (const float*)d_in[19];
    const float* head_b = (const float*)d_in[20];
    const float* key_pool = (const float*)d_in[21];
    const float* frequency = (const float*)d_in[22];
    const float* prompts = (const float*)d_in[23];
    const float* variance = (const float*)d_in[24];
    const float* inv_variance = (const float*)d_in[25];

    static bool attr_set = false;
    if (!attr_set) {
        cudaFuncSetAttribute(tc_gemm_kernel, cudaFuncAttributeMaxDynamicSharedMemorySize, GEMM_SMEM);
        attr_set = true;
    }

    float *px, *ph, *pqkv, *po, *pmlp, *pfeat;
    float *pwq, *pwp, *pw1, *pw2, *pwpc;
    cudaGetSymbolAddress((void**)&px,   g_x);
    cudaGetSymbolAddress((void**)&ph,   g_h);
    cudaGetSymbolAddress((void**)&pqkv, g_qkv);
    cudaGetSymbolAddress((void**)&po,   g_o);
    cudaGetSymbolAddress((void**)&pmlp, g_mlp);
    cudaGetSymbolAddress((void**)&pfeat, g_feat);
    cudaGetSymbolAddress((void**)&pwq,  g_wq);
    cudaGetSymbolAddress((void**)&pwp,  g_wp);
    cudaGetSymbolAddress((void**)&pw1,  g_w1);
    cudaGetSymbolAddress((void**)&pw2,  g_w2);
    cudaGetSymbolAddress((void**)&pwpc, g_wpc);

    // 0) pre-round weights to tf32 (once per launch; ~0.15 ms total)
    {
        long long nq = (long long)NLAYER * DMODEL * 3 * DMODEL;
        long long np = (long long)NLAYER * DMODEL * DMODEL;
        long long n1 = (long long)NLAYER * DMODEL * MLPD;
        long long npc = (long long)DMODEL * DMODEL;
        round_tf32_kernel<<<(int)((nq / 4 + 255) / 256), 256>>>(qkv_w, pwq, nq);
        round_tf32_kernel<<<(int)((np / 4 + 255) / 256), 256>>>(proj_w, pwp, np);
        round_tf32_kernel<<<(int)((n1 / 4 + 255) / 256), 256>>>(fc1_w, pw1, n1);
        round_tf32_kernel<<<(int)((n1 / 4 + 255) / 256), 256>>>(fc2_w, pw2, n1);
        round_tf32_kernel<<<(int)((npc / 4 + 255) / 256), 256>>>(patch_w, pwpc, npc);
    }

    // 1) patch embed
    patchify_kernel<<<(BATCH * 196 * DMODEL + 255) / 256, 256>>>(inputs);
    tc_gemm_kernel<<<dim3(DMODEL / TBN, (BATCH * 196 + TBM - 1) / TBM), 256, GEMM_SMEM>>>(
        pmlp, pwpc, patch_b, po, BATCH * 196, DMODEL, DMODEL, 0);
    embed_kernel<<<(BATCH * S1 * DMODEL + 255) / 256, 256>>>(cls_token, pos_embed);

    // 2) first ViT pass (S=197)
    run_vit(S1, BATCH * S1, ln1_w, ln1_b, pwq, qkv_b, pwp, proj_b,
            ln2_w, ln2_b, pw1, fc1_b, pw2, fc2_b, px, ph, pqkv, po, pmlp);

    // 3) routing
    ln_kernel<<<BATCH, 256>>>(px, pfeat, norm_w, norm_b, (long long)S1 * DMODEL, DMODEL);
    pool_stats_kernel<<<POOL, 256>>>(variance);
    logwn_kernel<<<1, 1>>>(frequency);
    quad_kernel<<<dim3(BATCH, POOL), 256>>>(key_pool, inv_variance);
    topk_kernel<<<1, 32>>>();

    // 4) splice prompts (S=222)
    build_sx_kernel<<<(BATCH * SMAX * DMODEL + 255) / 256, 256>>>(prompts, pos_embed);

    // 5) second ViT pass (S=222)
    run_vit(SMAX, BATCH * SMAX, ln1_w, ln1_b, pwq, qkv_b, pwp, proj_b,
            ln2_w, ln2_b, pw1, fc1_b, pw2, fc2_b, px, ph, pqkv, po, pmlp);

    // 6) final LN, mean over prompt tokens, head
    ln_kernel<<<BATCH * SMAX, 256>>>(px, ph, norm_w, norm_b, DMODEL, DMODEL);
    feat_kernel<<<(BATCH * DMODEL + 255) / 256, 256>>>();
    head_kernel<<<(BATCH * NCLS + 255) / 256, 256>>>(head_w, head_b, (float*)d_out);
}

// round 11
// speedup vs baseline: 1.8367x; 1.1608x over previous
#include <cuda_runtime.h>
#include <cuda_fp16.h>
#include <cstdint>

#define BATCH  32
#define SMAX   222
#define S1     197
#define DMODEL 768
#define NLAYER 12
#define NHEAD  12
#define HDIM   64
#define MLPD   3072
#define POOL   10
#define SEL    5
#define PLEN   5
#define NCLS   100
#define PSTRIDE 224

// ---------------- scratch (static device allocations; harness-legal) ----------------
__device__ float  g_x   [BATCH * SMAX * DMODEL];
__device__ float  g_x0  [BATCH * S1   * DMODEL];
__device__ float  g_h   [BATCH * SMAX * DMODEL];     // final-LN output (fp32)
__device__ __half g_hh  [BATCH * SMAX * DMODEL];     // in-layer LN output (half)
__device__ float  g_qkv [BATCH * SMAX * 3 * DMODEL];
__device__ __half g_oh  [BATCH * SMAX * DMODEL];     // attention output (half)
__device__ float  g_o   [BATCH * SMAX * DMODEL];     // patch-embed GEMM output (fp32)
__device__ __half g_mlph[BATCH * SMAX * MLPD];       // patchify / GELU output (half)
__device__ float  g_p   [BATCH * NHEAD * PSTRIDE * PSTRIDE];
__device__ float  g_feat[BATCH * DMODEL];
__device__ float  g_score[BATCH * POOL];
__device__ float  g_lognorm[POOL];
__device__ float  g_logwn[POOL];
__device__ int    g_topk[BATCH * SEL];

// fp16, TRANSPOSED ([N][K] K-major) weight copies, built once per launch
__device__ __half g_wq [NLAYER * DMODEL * 3 * DMODEL];
__device__ __half g_wp [NLAYER * DMODEL * DMODEL];
__device__ __half g_w1 [NLAYER * DMODEL * MLPD];
__device__ __half g_w2 [NLAYER * MLPD * DMODEL];
__device__ __half g_wpc[DMODEL * DMODEL];

// ---------------- reductions (blockDim == 256 assumed) ----------------
__device__ __forceinline__ float block_sum256(float v, float* red) {
    int lane = threadIdx.x & 31, wid = threadIdx.x >> 5;
    #pragma unroll
    for (int o = 16; o; o >>= 1) v += __shfl_xor_sync(0xffffffffu, v, o);
    if (lane == 0) red[wid] = v;
    __syncthreads();
    float r = (lane < 8) ? red[lane] : 0.f;
    #pragma unroll
    for (int o = 4; o; o >>= 1) r += __shfl_xor_sync(0xffffffffu, r, o);
    r = __shfl_sync(0xffffffffu, r, 0);
    __syncthreads();
    return r;
}

__device__ __forceinline__ float block_max256(float v, float* red) {
    int lane = threadIdx.x & 31, wid = threadIdx.x >> 5;
    #pragma unroll
    for (int o = 16; o; o >>= 1) v = fmaxf(v, __shfl_xor_sync(0xffffffffu, v, o));
    if (lane == 0) red[wid] = v;
    __syncthreads();
    float r = (lane < 8) ? red[lane] : -1e30f;
    #pragma unroll
    for (int o = 4; o; o >>= 1) r = fmaxf(r, __shfl_xor_sync(0xffffffffu, r, o));
    r = __shfl_sync(0xffffffffu, r, 0);
    __syncthreads();
    return r;
}

// ---------------- mma / cp.async helpers ----------------
__device__ __forceinline__ void mma_f16(float* c, const uint32_t* a, uint32_t b0, uint32_t b1) {
    asm volatile(
        "mma.sync.aligned.m16n8k16.row.col.f32.f16.f16.f32 "
        "{%0,%1,%2,%3}, {%4,%5,%6,%7}, {%8,%9}, {%0,%1,%2,%3};"
        : "+f"(c[0]), "+f"(c[1]), "+f"(c[2]), "+f"(c[3])
        : "r"(a[0]), "r"(a[1]), "r"(a[2]), "r"(a[3]), "r"(b0), "r"(b1));
}

__device__ __forceinline__ void cp_async16(void* smem_dst, const void* gsrc, int src_bytes) {
    unsigned sa = (unsigned)__cvta_generic_to_shared(smem_dst);
    asm volatile("cp.async.cg.shared.global [%0], [%1], 16, %2;"
                 :: "r"(sa), "l"(gsrc), "r"(src_bytes));
}
__device__ __forceinline__ void cp_commit() {
    asm volatile("cp.async.commit_group;");
}

// ---------------- weight transpose + fp16 round: dst[n*K+k] = h(src[k*N+n]) -------
__global__ void transpose_h_kernel(const float* __restrict__ src, __half* __restrict__ dst,
                                   int K, int N)
{
    __shared__ float tile[32][33];
    int l = blockIdx.z;
    const float* s = src + (size_t)l * K * N;
    __half* d = dst + (size_t)l * K * N;
    int k0 = blockIdx.y * 32, n0 = blockIdx.x * 32;
    for (int i = threadIdx.y; i < 32; i += 8)
        tile[i][threadIdx.x] = s[(size_t)(k0 + i) * N + n0 + threadIdx.x];
    __syncthreads();
    for (int i = threadIdx.y; i < 32; i += 8)
        d[(size_t)(n0 + i) * K + k0 + threadIdx.x] = __float2half_rn(tile[threadIdx.x][i]);
}

// ---------------- pipelined fp16 tensor-core GEMM ----------------
// C[M,N] = A[M,K] @ WT[N,K]^T + bias.  A, WT are fp16; accumulate fp32.
// mode 0: store fp32; mode 1: GELU -> store HALF (C is __half*); mode 2: += fp32.
// N % 128 == 0, K % 32 == 0; M guarded (cp.async zfill + epilogue guard).
#define TBM 128
#define TBN 128
#define TBK 32
#define HPITCH 40    // halves per row (32 + 8 pad); 80B rows, 16B-aligned

__global__ void __launch_bounds__(256) hgemm_kernel(
    const __half* __restrict__ A, const __half* __restrict__ WT,
    const float* __restrict__ bias, void* __restrict__ Cv,
    int M, int N, int K, int mode)
{
    __shared__ __half As[2][TBM * HPITCH];
    __shared__ __half Ws[2][TBN * HPITCH];

    int tid  = threadIdx.x;
    int warp = tid >> 5, lane = tid & 31;
    int g = lane >> 2, tig = lane & 3;
    int wm = (warp & 1) * 64;
    int wn = (warp >> 1) * 32;
    int row0 = blockIdx.y * TBM;
    int col0 = blockIdx.x * TBN;

    float acc[4][4][4];
    #pragma unroll
    for (int mt = 0; mt < 4; mt++)
        #pragma unroll
        for (int nt = 0; nt < 4; nt++)
            #pragma unroll
            for (int i = 0; i < 4; i++) acc[mt][nt][i] = 0.f;

    // tile loader: A rows 32 halves (64B) = 4 chunks; 512 chunks each for A and B
    auto load_tiles = [&](int k0, int buf) {
        __half* Ab = As[buf];
        __half* Wb = Ws[buf];
        #pragma unroll
        for (int i = 0; i < 2; i++) {
            int slot = tid + i * 256;          // 0..511
            int r = slot >> 2, c16 = slot & 3;
            int gm = row0 + r;
            const __half* src = A + (size_t)gm * K + k0 + c16 * 8;
            cp_async16(&Ab[r * HPITCH + c16 * 8], src, (gm < M) ? 16 : 0);
        }
        #pragma unroll
        for (int i = 0; i < 2; i++) {
            int slot = tid + i * 256;
            int n = slot >> 2, c16 = slot & 3;
            const __half* src = WT + (size_t)(col0 + n) * K + k0 + c16 * 8;
            cp_async16(&Wb[n * HPITCH + c16 * 8], src, 16);
        }
        cp_commit();
    };

    int T = K / TBK;
    load_tiles(0, 0);

    for (int t = 0; t < T; t++) {
        int buf = t & 1;
        if (t + 1 < T) {
            load_tiles((t + 1) * TBK, (t + 1) & 1);
            asm volatile("cp.async.wait_group 1;");
        } else {
            asm volatile("cp.async.wait_group 0;");
        }
        __syncthreads();

        const __half* Ab = As[buf];
        const __half* Wb = Ws[buf];
        #pragma unroll
        for (int ks = 0; ks < 2; ks++) {       // two k16 steps per 32-K tile
            int kk = ks * 16;
            uint32_t af[4][4];
            #pragma unroll
            for (int mt = 0; mt < 4; mt++) {
                int m0 = wm + mt * 16;
                af[mt][0] = *(const uint32_t*)&Ab[(m0 + g    ) * HPITCH + kk + tig * 2    ];
                af[mt][1] = *(const uint32_t*)&Ab[(m0 + g + 8) * HPITCH + kk + tig * 2    ];
                af[mt][2] = *(const uint32_t*)&Ab[(m0 + g    ) * HPITCH + kk + tig * 2 + 8];
                af[mt][3] = *(const uint32_t*)&Ab[(m0 + g + 8) * HPITCH + kk + tig * 2 + 8];
            }
            #pragma unroll
            for (int nt = 0; nt < 4; nt++) {
                int n0 = wn + nt * 8;
                uint32_t b0 = *(const uint32_t*)&Wb[(n0 + g) * HPITCH + kk + tig * 2    ];
                uint32_t b1 = *(const uint32_t*)&Wb[(n0 + g) * HPITCH + kk + tig * 2 + 8];
                #pragma unroll
                for (int mt = 0; mt < 4; mt++)
                    mma_f16(acc[mt][nt], af[mt], b0, b1);
            }
        }
        __syncthreads();
    }

    float* Cf = (float*)Cv;
    __half* Ch = (__half*)Cv;
    #pragma unroll
    for (int mt = 0; mt < 4; mt++) {
        #pragma unroll
        for (int nt = 0; nt < 4; nt++) {
            int gn = col0 + wn + nt * 8 + tig * 2;
            #pragma unroll
            for (int half_ = 0; half_ < 2; half_++) {
                int gm = row0 + wm + mt * 16 + g + half_ * 8;
                if (gm >= M) continue;
                #pragma unroll
                for (int cc = 0; cc < 2; cc++) {
                    float v = acc[mt][nt][half_ * 2 + cc] + bias[gn + cc];
                    size_t off = (size_t)gm * N + gn + cc;
                    if (mode == 1) {
                        v = 0.5f * v * (1.0f + erff(v * 0.70710678118654752f));
                        Ch[off] = __float2half_rn(v);
                    } else if (mode == 2) {
                        Cf[off] += v;
                    } else {
                        Cf[off] = v;
                    }
                }
            }
        }
    }
}

// ---------------- LayerNorm over 768 ----------------
// half-output variant (feeds GEMM A)
__global__ void ln_h_kernel(const float* __restrict__ in, __half* __restrict__ out,
                            const float* __restrict__ w, const float* __restrict__ b)
{
    __shared__ float red[8];
    const float* x = in + (long long)blockIdx.x * DMODEL;
    __half* y = out + (long long)blockIdx.x * DMODEL;
    int t = threadIdx.x;
    float v0 = x[t], v1 = x[t + 256], v2 = x[t + 512];
    float mean = block_sum256(v0 + v1 + v2, red) * (1.f / 768.f);
    float d0 = v0 - mean, d1 = v1 - mean, d2 = v2 - mean;
    float var = block_sum256(d0 * d0 + d1 * d1 + d2 * d2, red) * (1.f / 768.f);
    float rstd = rsqrtf(var + 1e-6f);
    y[t]       = __float2half_rn(d0 * rstd * w[t]       + b[t]);
    y[t + 256] = __float2half_rn(d1 * rstd * w[t + 256] + b[t + 256]);
    y[t + 512] = __float2half_rn(d2 * rstd * w[t + 512] + b[t + 512]);
}

// fp32-output variant (routing feature / final LN)
__global__ void ln_f_kernel(const float* __restrict__ in, float* __restrict__ out,
                            const float* __restrict__ w, const float* __restrict__ b,
                            long long in_stride, long long out_stride)
{
    __shared__ float red[8];
    const float* x = in + (long long)blockIdx.x * in_stride;
    float* y = out + (long long)blockIdx.x * out_stride;
    int t = threadIdx.x;
    float v0 = x[t], v1 = x[t + 256], v2 = x[t + 512];
    float mean = block_sum256(v0 + v1 + v2, red) * (1.f / 768.f);
    float d0 = v0 - mean, d1 = v1 - mean, d2 = v2 - mean;
    float var = block_sum256(d0 * d0 + d1 * d1 + d2 * d2, red) * (1.f / 768.f);
    float rstd = rsqrtf(var + 1e-6f);
    y[t]       = d0 * rstd * w[t]       + b[t];
    y[t + 256] = d1 * rstd * w[t + 256] + b[t + 256];
    y[t + 512] = d2 * rstd * w[t + 512] + b[t + 512];
}

// ---------------- attention (coalesced, smem-tiled, P materialized, fp32) ---------
#define SPAD 68

__global__ void __launch_bounds__(256) score_kernel(const float* __restrict__ qkv, int S)
{
    __shared__ float Qs[32][SPAD];
    __shared__ float KsT[64][SPAD];
    int q0 = blockIdx.x * 32, h = blockIdx.y, b = blockIdx.z;
    int tid = threadIdx.x;
    int q = tid >> 3, kg = tid & 7;
    const float* base = qkv + (size_t)b * S * (3 * DMODEL) + h * HDIM;
    float* prow = g_p + (((size_t)b * NHEAD + h) * PSTRIDE) * PSTRIDE;

    #pragma unroll
    for (int i = 0; i < 2; i++) {
        int slot = tid + i * 256;
        int r = slot >> 4, c4 = (slot & 15) * 4;
        int gq = q0 + r;
        float4 v = make_float4(0.f, 0.f, 0.f, 0.f);
        if (gq < S) v = *reinterpret_cast<const float4*>(&base[(size_t)gq * (3 * DMODEL) + c4]);
        *reinterpret_cast<float4*>(&Qs[r][c4]) = v;
    }

    int ntile = (S + 63) >> 6;
    for (int kt = 0; kt < ntile; kt++) {
        int k0 = kt * 64;
        #pragma unroll
        for (int i = 0; i < 4; i++) {
            int slot = tid + i * 256;
            int r = slot >> 4, c4 = (slot & 15) * 4;
            int gk = k0 + r;
            float4 v = make_float4(0.f, 0.f, 0.f, 0.f);
            if (gk < S) v = *reinterpret_cast<const float4*>(&base[(size_t)gk * (3 * DMODEL) + DMODEL + c4]);
            KsT[c4 + 0][r] = v.x;
            KsT[c4 + 1][r] = v.y;
            KsT[c4 + 2][r] = v.z;
            KsT[c4 + 3][r] = v.w;
        }
        __syncthreads();

        float acc[8];
        #pragma unroll
        for (int j = 0; j < 8; j++) acc[j] = 0.f;
        #pragma unroll
        for (int d = 0; d < HDIM; d++) {
            float qa = Qs[q][d];
            float4 kv0 = *reinterpret_cast<const float4*>(&KsT[d][kg * 8]);
            float4 kv1 = *reinterpret_cast<const float4*>(&KsT[d][kg * 8 + 4]);
            acc[0] += qa * kv0.x; acc[1] += qa * kv0.y;
            acc[2] += qa * kv0.z; acc[3] += qa * kv0.w;
            acc[4] += qa * kv1.x; acc[5] += qa * kv1.y;
            acc[6] += qa * kv1.z; acc[7] += qa * kv1.w;
        }
        int gq = q0 + q;
        if (gq < S) {
            float* pw = prow + (size_t)gq * PSTRIDE + k0 + kg * 8;
            #pragma unroll
            for (int j = 0; j < 8; j++) {
                int gk = k0 + kg * 8 + j;
                if (gk < S) pw[j] = acc[j] * 0.125f;
            }
        }
        __syncthreads();
    }
}

__global__ void softmax_kernel(int S)
{
    __shared__ float red[8];
    int q = blockIdx.x, h = blockIdx.y, b = blockIdx.z;
    float* prow = g_p + ((((size_t)b * NHEAD + h) * PSTRIDE) + q) * PSTRIDE;
    int t = threadIdx.x;
    float v = (t < S) ? prow[t] : -1e30f;
    float mx = block_max256(v, red);
    float e = (t < S) ? expf(v - mx) : 0.f;
    float sum = block_sum256(e, red);
    if (t < S) prow[t] = e / sum;
}

// pv: output HALF (feeds proj GEMM)
__global__ void __launch_bounds__(256) pv_kernel(const float* __restrict__ qkv,
                                                 __half* __restrict__ o, int S)
{
    __shared__ float Ps[32][SPAD];
    __shared__ float Vs[64][SPAD];
    int q0 = blockIdx.x * 32, h = blockIdx.y, b = blockIdx.z;
    int tid = threadIdx.x;
    int q = tid >> 3, dg = tid & 7;
    const float* vbase = qkv + (size_t)b * S * (3 * DMODEL) + 2 * DMODEL + h * HDIM;
    const float* prow = g_p + (((size_t)b * NHEAD + h) * PSTRIDE) * PSTRIDE;

    float acc[8];
    #pragma unroll
    for (int j = 0; j < 8; j++) acc[j] = 0.f;

    int ntile = (S + 63) >> 6;
    for (int kt = 0; kt < ntile; kt++) {
        int k0 = kt * 64;
        #pragma unroll
        for (int i = 0; i < 2; i++) {
            int slot = tid + i * 256;
            int r = slot >> 4, c4 = (slot & 15) * 4;
            int gq = q0 + r;
            float4 v = make_float4(0.f, 0.f, 0.f, 0.f);
            if (gq < S) {
                #pragma unroll
                for (int c = 0; c < 4; c++) {
                    int gk = k0 + c4 + c;
                    ((float*)&v)[c] = (gk < S) ? prow[(size_t)gq * PSTRIDE + gk] : 0.f;
                }
            }
            *reinterpret_cast<float4*>(&Ps[r][c4]) = v;
        }
        #pragma unroll
        for (int i = 0; i < 4; i++) {
            int slot = tid + i * 256;
            int r = slot >> 4, c4 = (slot & 15) * 4;
            int gk = k0 + r;
            float4 v = make_float4(0.f, 0.f, 0.f, 0.f);
            if (gk < S) v = *reinterpret_cast<const float4*>(&vbase[(size_t)gk * (3 * DMODEL) + c4]);
            *reinterpret_cast<float4*>(&Vs[r][c4]) = v;
        }
        __syncthreads();

        #pragma unroll
        for (int k = 0; k < 64; k++) {
            float p = Ps[q][k];
            float4 v0 = *reinterpret_cast<const float4*>(&Vs[k][dg * 8]);
            float4 v1 = *reinterpret_cast<const float4*>(&Vs[k][dg * 8 + 4]);
            acc[0] += p * v0.x; acc[1] += p * v0.y;
            acc[2] += p * v0.z; acc[3] += p * v0.w;
            acc[4] += p * v1.x; acc[5] += p * v1.y;
            acc[6] += p * v1.z; acc[7] += p * v1.w;
        }
        __syncthreads();
    }

    int gq = q0 + q;
    if (gq < S) {
        __half* ow = o + ((size_t)(b * S + gq)) * DMODEL + h * HDIM + dg * 8;
        #pragma unroll
        for (int j = 0; j < 8; j++) ow[j] = __float2half_rn(acc[j]);
    }
}

// ---------------- patchify + embedding ----------------
__global__ void patchify_kernel(const float* __restrict__ in)
{
    size_t i = (size_t)blockIdx.x * 256 + threadIdx.x;
    if (i >= (size_t)BATCH * 196 * DMODEL) return;
    int v = (int)(i % DMODEL);
    size_t t = i / DMODEL;
    int p = (int)(t % 196);
    int b = (int)(t / 196);
    int c = v >> 8;
    int py = (v & 255) >> 4;
    int px = v & 15;
    int gy = p / 14, gx = p % 14;
    g_mlph[i] = __float2half_rn(in[(((size_t)b * 3 + c) * 224 + gy * 16 + py) * 224 + gx * 16 + px]);
}

__global__ void embed_kernel(const float* __restrict__ cls, const float* __restrict__ pos)
{
    size_t i = (size_t)blockIdx.x * 256 + threadIdx.x;
    if (i >= (size_t)BATCH * S1 * DMODEL) return;
    int d = (int)(i % DMODEL);
    size_t t = i / DMODEL;
    int s = (int)(t % S1);
    int b = (int)(t / S1);
    float v;
    if (s == 0) v = cls[d] + pos[d];
    else        v = g_o[((size_t)b * 196 + (s - 1)) * DMODEL + d] + pos[(size_t)s * DMODEL + d];
    g_x[i] = v;
    g_x0[i] = v;
}

// ---------------- routing ----------------
__global__ void pool_stats_kernel(const float* __restrict__ var)
{
    __shared__ float red[8];
    int p = blockIdx.x;
    const float* v = var + (size_t)p * DMODEL * DMODEL;
    float s = 0.f;
    for (int i = threadIdx.x; i < DMODEL * DMODEL; i += 256) { float t = v[i]; s += t * t; }
    float tot = block_sum256(s, red);
    if (threadIdx.x == 0) g_lognorm[p] = 0.25f * logf(tot);
}

__global__ void logwn_kernel(const float* __restrict__ freq)
{
    float m = freq[0];
    for (int i = 1; i < POOL; i++) m = fmaxf(m, freq[i]);
    float w[POOL]; float ss = 0.f;
    for (int i = 0; i < POOL; i++) { w[i] = m - freq[i]; ss += w[i] * w[i]; }
    float nz = fmaxf(sqrtf(ss), 1e-12f);
    for (int i = 0; i < POOL; i++) g_logwn[i] = logf(fmaxf(w[i] / nz, 1e-30f));
}

__global__ void quad_kernel(const float* __restrict__ keys, const float* __restrict__ inv_var)
{
    __shared__ float diff[DMODEL];
    __shared__ float red[8];
    int b = blockIdx.x, p = blockIdx.y;
    for (int i = threadIdx.x; i < DMODEL; i += 256)
        diff[i] = g_feat[b * DMODEL + i] - keys[p * DMODEL + i];
    __syncthreads();
    const float* M = inv_var + (size_t)p * DMODEL * DMODEL;
    float acc = 0.f;
    #pragma unroll
    for (int ei = 0; ei < 3; ei++) {
        int e = threadIdx.x + ei * 256;
        float inner = 0.f;
        for (int d = 0; d < DMODEL; d++)
            inner += diff[d] * M[(size_t)d * DMODEL + e];
        acc += inner * diff[e];
    }
    float quad = block_sum256(acc, red);
    if (threadIdx.x == 0)
        g_score[b * POOL + p] = -0.5f * quad + g_lognorm[p] + g_logwn[p];
}

__global__ void topk_kernel()
{
    int b = threadIdx.x;
    if (b >= BATCH) return;
    float s[POOL]; bool used[POOL];
    for (int p = 0; p < POOL; p++) { s[p] = g_score[b * POOL + p]; used[p] = false; }
    for (int i = 0; i < SEL; i++) {
        int best = 0; float bv = 3.0e38f;
        for (int p = 0; p < POOL; p++)
            if (!used[p] && s[p] < bv) { bv = s[p]; best = p; }
        used[best] = true;
        g_topk[b * SEL + i] = best;
    }
}

__global__ void build_sx_kernel(const float* __restrict__ prompts, const float* __restrict__ pos)
{
    size_t i = (size_t)blockIdx.x * 256 + threadIdx.x;
    if (i >= (size_t)BATCH * SMAX * DMODEL) return;
    int d = (int)(i % DMODEL);
    size_t t = i / DMODEL;
    int s = (int)(t % SMAX);
    int b = (int)(t / SMAX);
    float v;
    if (s == 0) {
        v = g_x0[(size_t)b * S1 * DMODEL + d];
    } else if (s <= SEL * PLEN) {
        int idx = s - 1;
        int pi = idx / PLEN, j = idx % PLEN;
        int pool = g_topk[b * SEL + pi];
        v = prompts[((size_t)pool * PLEN + j) * DMODEL + d] + pos[d];
    } else {
        v = g_x0[((size_t)b * S1 + (s - SEL * PLEN)) * DMODEL + d];
    }
    g_x[i] = v;
}

// ---------------- epilogue ----------------
__global__ void feat_kernel()
{
    int i = blockIdx.x * 256 + threadIdx.x;
    if (i >= BATCH * DMODEL) return;
    int b = i / DMODEL, d = i % DMODEL;
    float s = 0.f;
    for (int t = 1; t <= SEL * PLEN; t++)
        s += g_h[((size_t)b * SMAX + t) * DMODEL + d];
    g_feat[i] = s * (1.f / (SEL * PLEN));
}

__global__ void head_kernel(const float* __restrict__ hw, const float* __restrict__ hb,
                            float* __restrict__ out)
{
    int i = blockIdx.x * 256 + threadIdx.x;
    if (i >= BATCH * NCLS) return;
    int b = i / NCLS, n = i % NCLS;
    float acc = hb[n];
    for (int k = 0; k < DMODEL; k++) acc += g_feat[b * DMODEL + k] * hw[k * NCLS + n];
    out[i] = acc;
}

// ---------------- host orchestration ----------------
static void run_vit(int S, int M,
    const float* ln1w, const float* ln1b, const __half* qkvw, const float* qkvb,
    const __half* pw, const float* pb, const float* ln2w, const float* ln2b,
    const __half* f1w, const float* f1b, const __half* f2w, const float* f2b,
    float* px, __half* phh, float* pqkv, __half* poh, __half* pmlph)
{
    int gy = (M + TBM - 1) / TBM;
    int qt = (S + 31) / 32;
    for (int l = 0; l < NLAYER; l++) {
        ln_h_kernel<<<M, 256>>>(px, phh, ln1w + (size_t)l * DMODEL, ln1b + (size_t)l * DMODEL);
        hgemm_kernel<<<dim3(3 * DMODEL / TBN, gy), 256>>>(phh, qkvw + (size_t)l * DMODEL * 3 * DMODEL,
                                                          qkvb + (size_t)l * 3 * DMODEL, pqkv, M, 3 * DMODEL, DMODEL, 0);
        score_kernel<<<dim3(qt, NHEAD, BATCH), 256>>>(pqkv, S);
        softmax_kernel<<<dim3(S, NHEAD, BATCH), 256>>>(S);
        pv_kernel<<<dim3(qt, NHEAD, BATCH), 256>>>(pqkv, poh, S);
        hgemm_kernel<<<dim3(DMODEL / TBN, gy), 256>>>(poh, pw + (size_t)l * DMODEL * DMODEL,
                                                      pb + (size_t)l * DMODEL, px, M, DMODEL, DMODEL, 2);
        ln_h_kernel<<<M, 256>>>(px, phh, ln2w + (size_t)l * DMODEL, ln2b + (size_t)l * DMODEL);
        hgemm_kernel<<<dim3(MLPD / TBN, gy), 256>>>(phh, f1w + (size_t)l * DMODEL * MLPD,
                                                    f1b + (size_t)l * MLPD, pmlph, M, MLPD, DMODEL, 1);
        hgemm_kernel<<<dim3(DMODEL / TBN, gy), 256>>>(pmlph, f2w + (size_t)l * MLPD * DMODEL,
                                                      f2b + (size_t)l * DMODEL, px, M, DMODEL, MLPD, 2);
    }
}

extern "C" void kernel_launch(void* const* d_in, const int* in_sizes, int n_in,
                              void* d_out, int out_size)
{
    const float* inputs    = (const float*)d_in[0];
    const float* patch_w   = (const float*)d_in[1];
    const float* patch_b   = (const float*)d_in[2];
    const float* cls_token = (const float*)d_in[3];
    const float* pos_embed = (const float*)d_in[4];
    const float* ln1_w = (const float*)d_in[5];
    const float* ln1_b = (const float*)d_in[6];
    const float* qkv_w = (const float*)d_in[7];
    const float* qkv_b = (const float*)d_in[8];
    const float* proj_w = (const float*)d_in[9];
    const float* proj_b = (const float*)d_in[10];
    const float* ln2_w = (const float*)d_in[11];
    const float* ln2_b = (const float*)d_in[12];
    const float* fc1_w = (const float*)d_in[13];
    const float* fc1_b = (const float*)d_in[14];
    const float* fc2_w = (const float*)d_in[15];
    const float* fc2_b = (const float*)d_in[16];
    const float* norm_w = (const float*)d_in[17];
    const float* norm_b = (const float*)d_in[18];
    const float* head_w = (const float*)d_in[19];
    const float* head_b = (const float*)d_in[20];
    const float* key_pool = (const float*)d_in[21];
    const float* frequency = (const float*)d_in[22];
    const float* prompts = (const float*)d_in[23];
    const float* variance = (const float*)d_in[24];
    const float* inv_variance = (const float*)d_in[25];

    float *px, *ph, *pqkv, *po, *pfeat;
    __half *phh, *poh, *pmlph;
    __half *pwq, *pwp, *pw1, *pw2, *pwpc;
    cudaGetSymbolAddress((void**)&px,    g_x);
    cudaGetSymbolAddress((void**)&ph,    g_h);
    cudaGetSymbolAddress((void**)&phh,   g_hh);
    cudaGetSymbolAddress((void**)&pqkv,  g_qkv);
    cudaGetSymbolAddress((void**)&po,    g_o);
    cudaGetSymbolAddress((void**)&poh,   g_oh);
    cudaGetSymbolAddress((void**)&pmlph, g_mlph);
    cudaGetSymbolAddress((void**)&pfeat, g_feat);
    cudaGetSymbolAddress((void**)&pwq,   g_wq);
    cudaGetSymbolAddress((void**)&pwp,   g_wp);
    cudaGetSymbolAddress((void**)&pw1,   g_w1);
    cudaGetSymbolAddress((void**)&pw2,   g_w2);
    cudaGetSymbolAddress((void**)&pwpc,  g_wpc);

    // 0) weight prep: transpose to [N][K] + fp16 round (once per launch)
    {
        dim3 blk(32, 8);
        transpose_h_kernel<<<dim3(3 * DMODEL / 32, DMODEL / 32, NLAYER), blk>>>(qkv_w, pwq, DMODEL, 3 * DMODEL);
        transpose_h_kernel<<<dim3(DMODEL / 32, DMODEL / 32, NLAYER), blk>>>(proj_w, pwp, DMODEL, DMODEL);
        transpose_h_kernel<<<dim3(MLPD / 32, DMODEL / 32, NLAYER), blk>>>(fc1_w, pw1, DMODEL, MLPD);
        transpose_h_kernel<<<dim3(DMODEL / 32, MLPD / 32, NLAYER), blk>>>(fc2_w, pw2, MLPD, DMODEL);
        transpose_h_kernel<<<dim3(DMODEL / 32, DMODEL / 32, 1), blk>>>(patch_w, pwpc, DMODEL, DMODEL);
    }

    // 1) patch embed
    patchify_kernel<<<(BATCH * 196 * DMODEL + 255) / 256, 256>>>(inputs);
    hgemm_kernel<<<dim3(DMODEL / TBN, (BATCH * 196 + TBM - 1) / TBM), 256>>>(
        pmlph, pwpc, patch_b, po, BATCH * 196, DMODEL, DMODEL, 0);
    embed_kernel<<<(BATCH * S1 * DMODEL + 255) / 256, 256>>>(cls_token, pos_embed);

    // 2) first ViT pass (S=197)
    run_vit(S1, BATCH * S1, ln1_w, ln1_b, pwq, qkv_b, pwp, proj_b,
            ln2_w, ln2_b, pw1, fc1_b, pw2, fc2_b, px, phh, pqkv, poh, pmlph);

    // 3) routing
    ln_f_kernel<<<BATCH, 256>>>(px, pfeat, norm_w, norm_b, (long long)S1 * DMODEL, DMODEL);
    pool_stats_kernel<<<POOL, 256>>>(variance);
    logwn_kernel<<<1, 1>>>(frequency);
    quad_kernel<<<dim3(BATCH, POOL), 256>>>(key_pool, inv_variance);
    topk_kernel<<<1, 32>>>();

    // 4) splice prompts (S=222)
    build_sx_kernel<<<(BATCH * SMAX * DMODEL + 255) / 256, 256>>>(prompts, pos_embed);

    // 5) second ViT pass (S=222)
    run_vit(SMAX, BATCH * SMAX, ln1_w, ln1_b, pwq, qkv_b, pwp, proj_b,
            ln2_w, ln2_b, pw1, fc1_b, pw2, fc2_b, px, phh, pqkv, poh, pmlph);

    // 6) final LN, mean over prompt tokens, head
    ln_f_kernel<<<BATCH * SMAX, 256>>>(px, ph, norm_w, norm_b, DMODEL, DMODEL);
    feat_kernel<<<(BATCH * DMODEL + 255) / 256, 256>>>();
    head_kernel<<<(BATCH * NCLS + 255) / 256, 256>>>(head_w, head_b, (float*)d_out);
}

// round 15
// speedup vs baseline: 1.8711x; 1.0187x over previous
#include <cuda_runtime.h>
#include <cuda_fp16.h>
#include <cstdint>

#define BATCH  32
#define SMAX   222
#define S1     197
#define DMODEL 768
#define NLAYER 12
#define NHEAD  12
#define HDIM   64
#define MLPD   3072
#define POOL   10
#define SEL    5
#define PLEN   5
#define NCLS   100
#define PSTRIDE 224

// ---------------- scratch (static device allocations; harness-legal) ----------------
__device__ float  g_x   [BATCH * SMAX * DMODEL];
__device__ float  g_x0  [BATCH * S1   * DMODEL];
__device__ float  g_h   [BATCH * SMAX * DMODEL];     // final-LN output (fp32)
__device__ __half g_hh  [BATCH * SMAX * DMODEL];     // in-layer LN output (half)
__device__ float  g_qkv [BATCH * SMAX * 3 * DMODEL];
__device__ __half g_oh  [BATCH * SMAX * DMODEL];     // attention output (half)
__device__ float  g_o   [BATCH * SMAX * DMODEL];     // patch-embed GEMM output (fp32)
__device__ __half g_mlph[BATCH * SMAX * MLPD];       // patchify / GELU output (half)
__device__ float  g_p   [BATCH * NHEAD * PSTRIDE * PSTRIDE];
__device__ float  g_feat[BATCH * DMODEL];
__device__ float  g_score[BATCH * POOL];
__device__ float  g_lognorm[POOL];
__device__ float  g_logwn[POOL];
__device__ int    g_topk[BATCH * SEL];

// fp16, TRANSPOSED ([N][K] K-major) weight copies, built once per launch
__device__ __half g_wq [NLAYER * DMODEL * 3 * DMODEL];
__device__ __half g_wp [NLAYER * DMODEL * DMODEL];
__device__ __half g_w1 [NLAYER * DMODEL * MLPD];
__device__ __half g_w2 [NLAYER * MLPD * DMODEL];
__device__ __half g_wpc[DMODEL * DMODEL];

// ---------------- reductions (blockDim == 256 assumed) ----------------
__device__ __forceinline__ float block_sum256(float v, float* red) {
    int lane = threadIdx.x & 31, wid = threadIdx.x >> 5;
    #pragma unroll
    for (int o = 16; o; o >>= 1) v += __shfl_xor_sync(0xffffffffu, v, o);
    if (lane == 0) red[wid] = v;
    __syncthreads();
    float r = (lane < 8) ? red[lane] : 0.f;
    #pragma unroll
    for (int o = 4; o; o >>= 1) r += __shfl_xor_sync(0xffffffffu, r, o);
    r = __shfl_sync(0xffffffffu, r, 0);
    __syncthreads();
    return r;
}

__device__ __forceinline__ float block_max256(float v, float* red) {
    int lane = threadIdx.x & 31, wid = threadIdx.x >> 5;
    #pragma unroll
    for (int o = 16; o; o >>= 1) v = fmaxf(v, __shfl_xor_sync(0xffffffffu, v, o));
    if (lane == 0) red[wid] = v;
    __syncthreads();
    float r = (lane < 8) ? red[lane] : -1e30f;
    #pragma unroll
    for (int o = 4; o; o >>= 1) r = fmaxf(r, __shfl_xor_sync(0xffffffffu, r, o));
    r = __shfl_sync(0xffffffffu, r, 0);
    __syncthreads();
    return r;
}

// ---------------- mma / cp.async / ldmatrix helpers ----------------
__device__ __forceinline__ void mma_f16(float* c, const uint32_t* a, uint32_t b0, uint32_t b1) {
    asm volatile(
        "mma.sync.aligned.m16n8k16.row.col.f32.f16.f16.f32 "
        "{%0,%1,%2,%3}, {%4,%5,%6,%7}, {%8,%9}, {%0,%1,%2,%3};"
        : "+f"(c[0]), "+f"(c[1]), "+f"(c[2]), "+f"(c[3])
        : "r"(a[0]), "r"(a[1]), "r"(a[2]), "r"(a[3]), "r"(b0), "r"(b1));
}

__device__ __forceinline__ void ldsm_x4(uint32_t& r0, uint32_t& r1, uint32_t& r2, uint32_t& r3,
                                        uint32_t addr) {
    asm volatile("ldmatrix.sync.aligned.m8n8.x4.shared.b16 {%0,%1,%2,%3}, [%4];"
                 : "=r"(r0), "=r"(r1), "=r"(r2), "=r"(r3) : "r"(addr));
}

__device__ __forceinline__ void cp_async16(void* smem_dst, const void* gsrc, int src_bytes) {
    unsigned sa = (unsigned)__cvta_generic_to_shared(smem_dst);
    asm volatile("cp.async.cg.shared.global [%0], [%1], 16, %2;"
                 :: "r"(sa), "l"(gsrc), "r"(src_bytes));
}
__device__ __forceinline__ void cp_commit() {
    asm volatile("cp.async.commit_group;");
}

// ---------------- weight transpose + fp16 round: dst[n*K+k] = h(src[k*N+n]) -------
__global__ void transpose_h_kernel(const float* __restrict__ src, __half* __restrict__ dst,
                                   int K, int N)
{
    __shared__ float tile[32][33];
    int l = blockIdx.z;
    const float* s = src + (size_t)l * K * N;
    __half* d = dst + (size_t)l * K * N;
    int k0 = blockIdx.y * 32, n0 = blockIdx.x * 32;
    for (int i = threadIdx.y; i < 32; i += 8)
        tile[i][threadIdx.x] = s[(size_t)(k0 + i) * N + n0 + threadIdx.x];
    __syncthreads();
    for (int i = threadIdx.y; i < 32; i += 8)
        d[(size_t)(n0 + i) * K + k0 + threadIdx.x] = __float2half_rn(tile[threadIdx.x][i]);
}

// ---------------- pipelined fp16 tensor-core GEMM (ldmatrix fragments) ----------------
// C[M,N] = A[M,K] @ WT[N,K]^T + bias.  A, WT fp16; accumulate fp32.
// mode 0: store fp32; mode 1: GELU -> store HALF (C is __half*); mode 2: += fp32.
#define TBM 128
#define TBN 128
#define TBK 32
#define HPITCH 40    // halves per row (32 + 8 pad); 80B rows: LDSM rows hit disjoint bank quads

__global__ void __launch_bounds__(256) hgemm_kernel(
    const __half* __restrict__ A, const __half* __restrict__ WT,
    const float* __restrict__ bias, void* __restrict__ Cv,
    int M, int N, int K, int mode)
{
    __shared__ __half As[2][TBM * HPITCH];
    __shared__ __half Ws[2][TBN * HPITCH];

    int tid  = threadIdx.x;
    int warp = tid >> 5, lane = tid & 31;
    int g = lane >> 2, tig = lane & 3;
    int wm = (warp & 1) * 64;
    int wn = (warp >> 1) * 32;
    int row0 = blockIdx.y * TBM;
    int col0 = blockIdx.x * TBN;

    // ldmatrix per-lane byte offsets within a tile (halves * 2 bytes)
    // A: row = (lane&15), kcol = (lane>>4)*8
    uint32_t a_off = (uint32_t)(((lane & 15) * HPITCH + (lane >> 4) * 8) * 2);
    // B: row = (lane&7) + ((lane>>4)&1)*8, kcol = ((lane>>3)&1)*8
    uint32_t b_off = (uint32_t)((((lane & 7) + ((lane >> 4) & 1) * 8) * HPITCH + ((lane >> 3) & 1) * 8) * 2);

    float acc[4][4][4];
    #pragma unroll
    for (int mt = 0; mt < 4; mt++)
        #pragma unroll
        for (int nt = 0; nt < 4; nt++)
            #pragma unroll
            for (int i = 0; i < 4; i++) acc[mt][nt][i] = 0.f;

    auto load_tiles = [&](int k0, int buf) {
        __half* Ab = As[buf];
        __half* Wb = Ws[buf];
        #pragma unroll
        for (int i = 0; i < 2; i++) {
            int slot = tid + i * 256;          // 0..511
            int r = slot >> 2, c16 = slot & 3;
            int gm = row0 + r;
            const __half* src = A + (size_t)gm * K + k0 + c16 * 8;
            cp_async16(&Ab[r * HPITCH + c16 * 8], src, (gm < M) ? 16 : 0);
        }
        #pragma unroll
        for (int i = 0; i < 2; i++) {
            int slot = tid + i * 256;
            int n = slot >> 2, c16 = slot & 3;
            const __half* src = WT + (size_t)(col0 + n) * K + k0 + c16 * 8;
            cp_async16(&Wb[n * HPITCH + c16 * 8], src, 16);
        }
        cp_commit();
    };

    int T = K / TBK;
    load_tiles(0, 0);

    for (int t = 0; t < T; t++) {
        int buf = t & 1;
        if (t + 1 < T) {
            load_tiles((t + 1) * TBK, (t + 1) & 1);
            asm volatile("cp.async.wait_group 1;");
        } else {
            asm volatile("cp.async.wait_group 0;");
        }
        __syncthreads();

        uint32_t abase = (uint32_t)__cvta_generic_to_shared(&As[buf][0]);
        uint32_t bbase = (uint32_t)__cvta_generic_to_shared(&Ws[buf][0]);
        #pragma unroll
        for (int ks = 0; ks < 2; ks++) {       // two k16 steps per 32-K tile
            int kk = ks * 16;
            uint32_t af[4][4];
            #pragma unroll
            for (int mt = 0; mt < 4; mt++) {
                uint32_t addr = abase + (uint32_t)(((wm + mt * 16) * HPITCH + kk) * 2) + a_off;
                ldsm_x4(af[mt][0], af[mt][1], af[mt][2], af[mt][3], addr);
            }
            uint32_t b0[4], b1[4];
            #pragma unroll
            for (int p = 0; p < 2; p++) {      // each x4 covers two n8 tiles
                uint32_t addr = bbase + (uint32_t)(((wn + p * 16) * HPITCH + kk) * 2) + b_off;
                ldsm_x4(b0[p * 2], b1[p * 2], b0[p * 2 + 1], b1[p * 2 + 1], addr);
            }
            #pragma unroll
            for (int nt = 0; nt < 4; nt++)
                #pragma unroll
                for (int mt = 0; mt < 4; mt++)
                    mma_f16(acc[mt][nt], af[mt], b0[nt], b1[nt]);
        }
        __syncthreads();
    }

    float* Cf = (float*)Cv;
    __half* Ch = (__half*)Cv;
    #pragma unroll
    for (int mt = 0; mt < 4; mt++) {
        #pragma unroll
        for (int nt = 0; nt < 4; nt++) {
            int gn = col0 + wn + nt * 8 + tig * 2;
            #pragma unroll
            for (int half_ = 0; half_ < 2; half_++) {
                int gm = row0 + wm + mt * 16 + g + half_ * 8;
                if (gm >= M) continue;
                #pragma unroll
                for (int cc = 0; cc < 2; cc++) {
                    float v = acc[mt][nt][half_ * 2 + cc] + bias[gn + cc];
                    size_t off = (size_t)gm * N + gn + cc;
                    if (mode == 1) {
                        v = 0.5f * v * (1.0f + erff(v * 0.70710678118654752f));
                        Ch[off] = __float2half_rn(v);
                    } else if (mode == 2) {
                        Cf[off] += v;
                    } else {
                        Cf[off] = v;
                    }
                }
            }
        }
    }
}

// ---------------- LayerNorm over 768 ----------------
__global__ void ln_h_kernel(const float* __restrict__ in, __half* __restrict__ out,
                            const float* __restrict__ w, const float* __restrict__ b)
{
    __shared__ float red[8];
    const float* x = in + (long long)blockIdx.x * DMODEL;
    __half* y = out + (long long)blockIdx.x * DMODEL;
    int t = threadIdx.x;
    float v0 = x[t], v1 = x[t + 256], v2 = x[t + 512];
    float mean = block_sum256(v0 + v1 + v2, red) * (1.f / 768.f);
    float d0 = v0 - mean, d1 = v1 - mean, d2 = v2 - mean;
    float var = block_sum256(d0 * d0 + d1 * d1 + d2 * d2, red) * (1.f / 768.f);
    float rstd = rsqrtf(var + 1e-6f);
    y[t]       = __float2half_rn(d0 * rstd * w[t]       + b[t]);
    y[t + 256] = __float2half_rn(d1 * rstd * w[t + 256] + b[t + 256]);
    y[t + 512] = __float2half_rn(d2 * rstd * w[t + 512] + b[t + 512]);
}

__global__ void ln_f_kernel(const float* __restrict__ in, float* __restrict__ out,
                            const float* __restrict__ w, const float* __restrict__ b,
                            long long in_stride, long long out_stride)
{
    __shared__ float red[8];
    const float* x = in + (long long)blockIdx.x * in_stride;
    float* y = out + (long long)blockIdx.x * out_stride;
    int t = threadIdx.x;
    float v0 = x[t], v1 = x[t + 256], v2 = x[t + 512];
    float mean = block_sum256(v0 + v1 + v2, red) * (1.f / 768.f);
    float d0 = v0 - mean, d1 = v1 - mean, d2 = v2 - mean;
    float var = block_sum256(d0 * d0 + d1 * d1 + d2 * d2, red) * (1.f / 768.f);
    float rstd = rsqrtf(var + 1e-6f);
    y[t]       = d0 * rstd * w[t]       + b[t];
    y[t + 256] = d1 * rstd * w[t + 256] + b[t + 256];
    y[t + 512] = d2 * rstd * w[t + 512] + b[t + 512];
}

// ---------------- attention (coalesced, smem-tiled, P materialized, fp32) ---------
#define SPAD 68

__global__ void __launch_bounds__(256) score_kernel(const float* __restrict__ qkv, int S)
{
    __shared__ float Qs[32][SPAD];
    __shared__ float KsT[64][SPAD];
    int q0 = blockIdx.x * 32, h = blockIdx.y, b = blockIdx.z;
    int tid = threadIdx.x;
    int q = tid >> 3, kg = tid & 7;
    const float* base = qkv + (size_t)b * S * (3 * DMODEL) + h * HDIM;
    float* prow = g_p + (((size_t)b * NHEAD + h) * PSTRIDE) * PSTRIDE;

    #pragma unroll
    for (int i = 0; i < 2; i++) {
        int slot = tid + i * 256;
        int r = slot >> 4, c4 = (slot & 15) * 4;
        int gq = q0 + r;
        float4 v = make_float4(0.f, 0.f, 0.f, 0.f);
        if (gq < S) v = *reinterpret_cast<const float4*>(&base[(size_t)gq * (3 * DMODEL) + c4]);
        *reinterpret_cast<float4*>(&Qs[r][c4]) = v;
    }

    int ntile = (S + 63) >> 6;
    for (int kt = 0; kt < ntile; kt++) {
        int k0 = kt * 64;
        #pragma unroll
        for (int i = 0; i < 4; i++) {
            int slot = tid + i * 256;
            int r = slot >> 4, c4 = (slot & 15) * 4;
            int gk = k0 + r;
            float4 v = make_float4(0.f, 0.f, 0.f, 0.f);
            if (gk < S) v = *reinterpret_cast<const float4*>(&base[(size_t)gk * (3 * DMODEL) + DMODEL + c4]);
            KsT[c4 + 0][r] = v.x;
            KsT[c4 + 1][r] = v.y;
            KsT[c4 + 2][r] = v.z;
            KsT[c4 + 3][r] = v.w;
        }
        __syncthreads();

        float acc[8];
        #pragma unroll
        for (int j = 0; j < 8; j++) acc[j] = 0.f;
        #pragma unroll
        for (int d = 0; d < HDIM; d++) {
            float qa = Qs[q][d];
            float4 kv0 = *reinterpret_cast<const float4*>(&KsT[d][kg * 8]);
            float4 kv1 = *reinterpret_cast<const float4*>(&KsT[d][kg * 8 + 4]);
            acc[0] += qa * kv0.x; acc[1] += qa * kv0.y;
            acc[2] += qa * kv0.z; acc[3] += qa * kv0.w;
            acc[4] += qa * kv1.x; acc[5] += qa * kv1.y;
            acc[6] += qa * kv1.z; acc[7] += qa * kv1.w;
        }
        int gq = q0 + q;
        if (gq < S) {
            float* pw = prow + (size_t)gq * PSTRIDE + k0 + kg * 8;
            #pragma unroll
            for (int j = 0; j < 8; j++) {
                int gk = k0 + kg * 8 + j;
                if (gk < S) pw[j] = acc[j] * 0.125f;
            }
        }
        __syncthreads();
    }
}

__global__ void softmax_kernel(int S)
{
    __shared__ float red[8];
    int q = blockIdx.x, h = blockIdx.y, b = blockIdx.z;
    float* prow = g_p + ((((size_t)b * NHEAD + h) * PSTRIDE) + q) * PSTRIDE;
    int t = threadIdx.x;
    float v = (t < S) ? prow[t] : -1e30f;
    float mx = block_max256(v, red);
    float e = (t < S) ? expf(v - mx) : 0.f;
    float sum = block_sum256(e, red);
    if (t < S) prow[t] = e / sum;
}

// pv: output HALF (feeds proj GEMM)
__global__ void __launch_bounds__(256) pv_kernel(const float* __restrict__ qkv,
                                                 __half* __restrict__ o, int S)
{
    __shared__ float Ps[32][SPAD];
    __shared__ float Vs[64][SPAD];
    int q0 = blockIdx.x * 32, h = blockIdx.y, b = blockIdx.z;
    int tid = threadIdx.x;
    int q = tid >> 3, dg = tid & 7;
    const float* vbase = qkv + (size_t)b * S * (3 * DMODEL) + 2 * DMODEL + h * HDIM;
    const float* prow = g_p + (((size_t)b * NHEAD + h) * PSTRIDE) * PSTRIDE;

    float acc[8];
    #pragma unroll
    for (int j = 0; j < 8; j++) acc[j] = 0.f;

    int ntile = (S + 63) >> 6;
    for (int kt = 0; kt < ntile; kt++) {
        int k0 = kt * 64;
        #pragma unroll
        for (int i = 0; i < 2; i++) {
            int slot = tid + i * 256;
            int r = slot >> 4, c4 = (slot & 15) * 4;
            int gq = q0 + r;
            float4 v = make_float4(0.f, 0.f, 0.f, 0.f);
            if (gq < S) {
                #pragma unroll
                for (int c = 0; c < 4; c++) {
                    int gk = k0 + c4 + c;
                    ((float*)&v)[c] = (gk < S) ? prow[(size_t)gq * PSTRIDE + gk] : 0.f;
                }
            }
            *reinterpret_cast<float4*>(&Ps[r][c4]) = v;
        }
        #pragma unroll
        for (int i = 0; i < 4; i++) {
            int slot = tid + i * 256;
            int r = slot >> 4, c4 = (slot & 15) * 4;
            int gk = k0 + r;
            float4 v = make_float4(0.f, 0.f, 0.f, 0.f);
            if (gk < S) v = *reinterpret_cast<const float4*>(&vbase[(size_t)gk * (3 * DMODEL) + c4]);
            *reinterpret_cast<float4*>(&Vs[r][c4]) = v;
        }
        __syncthreads();

        #pragma unroll
        for (int k = 0; k < 64; k++) {
            float p = Ps[q][k];
            float4 v0 = *reinterpret_cast<const float4*>(&Vs[k][dg * 8]);
            float4 v1 = *reinterpret_cast<const float4*>(&Vs[k][dg * 8 + 4]);
            acc[0] += p * v0.x; acc[1] += p * v0.y;
            acc[2] += p * v0.z; acc[3] += p * v0.w;
            acc[4] += p * v1.x; acc[5] += p * v1.y;
            acc[6] += p * v1.z; acc[7] += p * v1.w;
        }
        __syncthreads();
    }

    int gq = q0 + q;
    if (gq < S) {
        __half* ow = o + ((size_t)(b * S + gq)) * DMODEL + h * HDIM + dg * 8;
        #pragma unroll
        for (int j = 0; j < 8; j++) ow[j] = __float2half_rn(acc[j]);
    }
}

// ---------------- patchify + embedding ----------------
__global__ void patchify_kernel(const float* __restrict__ in)
{
    size_t i = (size_t)blockIdx.x * 256 + threadIdx.x;
    if (i >= (size_t)BATCH * 196 * DMODEL) return;
    int v = (int)(i % DMODEL);
    size_t t = i / DMODEL;
    int p = (int)(t % 196);
    int b = (int)(t / 196);
    int c = v >> 8;
    int py = (v & 255) >> 4;
    int px = v & 15;
    int gy = p / 14, gx = p % 14;
    g_mlph[i] = __float2half_rn(in[(((size_t)b * 3 + c) * 224 + gy * 16 + py) * 224 + gx * 16 + px]);
}

__global__ void embed_kernel(const float* __restrict__ cls, const float* __restrict__ pos)
{
    size_t i = (size_t)blockIdx.x * 256 + threadIdx.x;
    if (i >= (size_t)BATCH * S1 * DMODEL) return;
    int d = (int)(i % DMODEL);
    size_t t = i / DMODEL;
    int s = (int)(t % S1);
    int b = (int)(t / S1);
    float v;
    if (s == 0) v = cls[d] + pos[d];
    else        v = g_o[((size_t)b * 196 + (s - 1)) * DMODEL + d] + pos[(size_t)s * DMODEL + d];
    g_x[i] = v;
    g_x0[i] = v;
}

// ---------------- routing ----------------
__global__ void pool_stats_kernel(const float* __restrict__ var)
{
    __shared__ float red[8];
    int p = blockIdx.x;
    const float* v = var + (size_t)p * DMODEL * DMODEL;
    float s = 0.f;
    for (int i = threadIdx.x; i < DMODEL * DMODEL; i += 256) { float t = v[i]; s += t * t; }
    float tot = block_sum256(s, red);
    if (threadIdx.x == 0) g_lognorm[p] = 0.25f * logf(tot);
}

__global__ void logwn_kernel(const float* __restrict__ freq)
{
    float m = freq[0];
    for (int i = 1; i < POOL; i++) m = fmaxf(m, freq[i]);
    float w[POOL]; float ss = 0.f;
    for (int i = 0; i < POOL; i++) { w[i] = m - freq[i]; ss += w[i] * w[i]; }
    float nz = fmaxf(sqrtf(ss), 1e-12f);
    for (int i = 0; i < POOL; i++) g_logwn[i] = logf(fmaxf(w[i] / nz, 1e-30f));
}

__global__ void quad_kernel(const float* __restrict__ keys, const float* __restrict__ inv_var)
{
    __shared__ float diff[DMODEL];
    __shared__ float red[8];
    int b = blockIdx.x, p = blockIdx.y;
    for (int i = threadIdx.x; i < DMODEL; i += 256)
        diff[i] = g_feat[b * DMODEL + i] - keys[p * DMODEL + i];
    __syncthreads();
    const float* M = inv_var + (size_t)p * DMODEL * DMODEL;
    float acc = 0.f;
    #pragma unroll
    for (int ei = 0; ei < 3; ei++) {
        int e = threadIdx.x + ei * 256;
        float inner = 0.f;
        for (int d = 0; d < DMODEL; d++)
            inner += diff[d] * M[(size_t)d * DMODEL + e];
        acc += inner * diff[e];
    }
    float quad = block_sum256(acc, red);
    if (threadIdx.x == 0)
        g_score[b * POOL + p] = -0.5f * quad + g_lognorm[p] + g_logwn[p];
}

__global__ void topk_kernel()
{
    int b = threadIdx.x;
    if (b >= BATCH) return;
    float s[POOL]; bool used[POOL];
    for (int p = 0; p < POOL; p++) { s[p] = g_score[b * POOL + p]; used[p] = false; }
    for (int i = 0; i < SEL; i++) {
        int best = 0; float bv = 3.0e38f;
        for (int p = 0; p < POOL; p++)
            if (!used[p] && s[p] < bv) { bv = s[p]; best = p; }
        used[best] = true;
        g_topk[b * SEL + i] = best;
    }
}

__global__ void build_sx_kernel(const float* __restrict__ prompts, const float* __restrict__ pos)
{
    size_t i = (size_t)blockIdx.x * 256 + threadIdx.x;
    if (i >= (size_t)BATCH * SMAX * DMODEL) return;
    int d = (int)(i % DMODEL);
    size_t t = i / DMODEL;
    int s = (int)(t % SMAX);
    int b = (int)(t / SMAX);
    float v;
    if (s == 0) {
        v = g_x0[(size_t)b * S1 * DMODEL + d];
    } else if (s <= SEL * PLEN) {
        int idx = s - 1;
        int pi = idx / PLEN, j = idx % PLEN;
        int pool = g_topk[b * SEL + pi];
        v = prompts[((size_t)pool * PLEN + j) * DMODEL + d] + pos[d];
    } else {
        v = g_x0[((size_t)b * S1 + (s - SEL * PLEN)) * DMODEL + d];
    }
    g_x[i] = v;
}

// ---------------- epilogue ----------------
__global__ void feat_kernel()
{
    int i = blockIdx.x * 256 + threadIdx.x;
    if (i >= BATCH * DMODEL) return;
    int b = i / DMODEL, d = i % DMODEL;
    float s = 0.f;
    for (int t = 1; t <= SEL * PLEN; t++)
        s += g_h[((size_t)b * SMAX + t) * DMODEL + d];
    g_feat[i] = s * (1.f / (SEL * PLEN));
}

__global__ void head_kernel(const float* __restrict__ hw, const float* __restrict__ hb,
                            float* __restrict__ out)
{
    int i = blockIdx.x * 256 + threadIdx.x;
    if (i >= BATCH * NCLS) return;
    int b = i / NCLS, n = i % NCLS;
    float acc = hb[n];
    for (int k = 0; k < DMODEL; k++) acc += g_feat[b * DMODEL + k] * hw[k * NCLS + n];
    out[i] = acc;
}

// ---------------- host orchestration ----------------
static void run_vit(int S, int M,
    const float* ln1w, const float* ln1b, const __half* qkvw, const float* qkvb,
    const __half* pw, const float* pb, const float* ln2w, const float* ln2b,
    const __half* f1w, const float* f1b, const __half* f2w, const float* f2b,
    float* px, __half* phh, float* pqkv, __half* poh, __half* pmlph)
{
    int gy = (M + TBM - 1) / TBM;
    int qt = (S + 31) / 32;
    for (int l = 0; l < NLAYER; l++) {
        ln_h_kernel<<<M, 256>>>(px, phh, ln1w + (size_t)l * DMODEL, ln1b + (size_t)l * DMODEL);
        hgemm_kernel<<<dim3(3 * DMODEL / TBN, gy), 256>>>(phh, qkvw + (size_t)l * DMODEL * 3 * DMODEL,
                                                          qkvb + (size_t)l * 3 * DMODEL, pqkv, M, 3 * DMODEL, DMODEL, 0);
        score_kernel<<<dim3(qt, NHEAD, BATCH), 256>>>(pqkv, S);
        softmax_kernel<<<dim3(S, NHEAD, BATCH), 256>>>(S);
        pv_kernel<<<dim3(qt, NHEAD, BATCH), 256>>>(pqkv, poh, S);
        hgemm_kernel<<<dim3(DMODEL / TBN, gy), 256>>>(poh, pw + (size_t)l * DMODEL * DMODEL,
                                                      pb + (size_t)l * DMODEL, px, M, DMODEL, DMODEL, 2);
        ln_h_kernel<<<M, 256>>>(px, phh, ln2w + (size_t)l * DMODEL, ln2b + (size_t)l * DMODEL);
        hgemm_kernel<<<dim3(MLPD / TBN, gy), 256>>>(phh, f1w + (size_t)l * DMODEL * MLPD,
                                                    f1b + (size_t)l * MLPD, pmlph, M, MLPD, DMODEL, 1);
        hgemm_kernel<<<dim3(DMODEL / TBN, gy), 256>>>(pmlph, f2w + (size_t)l * MLPD * DMODEL,
                                                      f2b + (size_t)l * DMODEL, px, M, DMODEL, MLPD, 2);
    }
}

extern "C" void kernel_launch(void* const* d_in, const int* in_sizes, int n_in,
                              void* d_out, int out_size)
{
    const float* inputs    = (const float*)d_in[0];
    const float* patch_w   = (const float*)d_in[1];
    const float* patch_b   = (const float*)d_in[2];
    const float* cls_token = (const float*)d_in[3];
    const float* pos_embed = (const float*)d_in[4];
    const float* ln1_w = (const float*)d_in[5];
    const float* ln1_b = (const float*)d_in[6];
    const float* qkv_w = (const float*)d_in[7];
    const float* qkv_b = (const float*)d_in[8];
    const float* proj_w = (const float*)d_in[9];
    const float* proj_b = (const float*)d_in[10];
    const float* ln2_w = (const float*)d_in[11];
    const float* ln2_b = (const float*)d_in[12];
    const float* fc1_w = (const float*)d_in[13];
    const float* fc1_b = (const float*)d_in[14];
    const float* fc2_w = (const float*)d_in[15];
    const float* fc2_b = (const float*)d_in[16];
    const float* norm_w = (const float*)d_in[17];
    const float* norm_b = (const float*)d_in[18];
    const float* head_w = (const float*)d_in[19];
    const float* head_b = (const float*)d_in[20];
    const float* key_pool = (const float*)d_in[21];
    const float* frequency = (const float*)d_in[22];
    const float* prompts = (const float*)d_in[23];
    const float* variance = (const float*)d_in[24];
    const float* inv_variance = (const float*)d_in[25];

    float *px, *ph, *pqkv, *po, *pfeat;
    __half *phh, *poh, *pmlph;
    __half *pwq, *pwp, *pw1, *pw2, *pwpc;
    cudaGetSymbolAddress((void**)&px,    g_x);
    cudaGetSymbolAddress((void**)&ph,    g_h);
    cudaGetSymbolAddress((void**)&phh,   g_hh);
    cudaGetSymbolAddress((void**)&pqkv,  g_qkv);
    cudaGetSymbolAddress((void**)&po,    g_o);
    cudaGetSymbolAddress((void**)&poh,   g_oh);
    cudaGetSymbolAddress((void**)&pmlph, g_mlph);
    cudaGetSymbolAddress((void**)&pfeat, g_feat);
    cudaGetSymbolAddress((void**)&pwq,   g_wq);
    cudaGetSymbolAddress((void**)&pwp,   g_wp);
    cudaGetSymbolAddress((void**)&pw1,   g_w1);
    cudaGetSymbolAddress((void**)&pw2,   g_w2);
    cudaGetSymbolAddress((void**)&pwpc,  g_wpc);

    // 0) weight prep: transpose to [N][K] + fp16 round (once per launch)
    {
        dim3 blk(32, 8);
        transpose_h_kernel<<<dim3(3 * DMODEL / 32, DMODEL / 32, NLAYER), blk>>>(qkv_w, pwq, DMODEL, 3 * DMODEL);
        transpose_h_kernel<<<dim3(DMODEL / 32, DMODEL / 32, NLAYER), blk>>>(proj_w, pwp, DMODEL, DMODEL);
        transpose_h_kernel<<<dim3(MLPD / 32, DMODEL / 32, NLAYER), blk>>>(fc1_w, pw1, DMODEL, MLPD);
        transpose_h_kernel<<<dim3(DMODEL / 32, MLPD / 32, NLAYER), blk>>>(fc2_w, pw2, MLPD, DMODEL);
        transpose_h_kernel<<<dim3(DMODEL / 32, DMODEL / 32, 1), blk>>>(patch_w, pwpc, DMODEL, DMODEL);
    }

    // 1) patch embed
    patchify_kernel<<<(BATCH * 196 * DMODEL + 255) / 256, 256>>>(inputs);
    hgemm_kernel<<<dim3(DMODEL / TBN, (BATCH * 196 + TBM - 1) / TBM), 256>>>(
        pmlph, pwpc, patch_b, po, BATCH * 196, DMODEL, DMODEL, 0);
    embed_kernel<<<(BATCH * S1 * DMODEL + 255) / 256, 256>>>(cls_token, pos_embed);

    // 2) first ViT pass (S=197)
    run_vit(S1, BATCH * S1, ln1_w, ln1_b, pwq, qkv_b, pwp, proj_b,
            ln2_w, ln2_b, pw1, fc1_b, pw2, fc2_b, px, phh, pqkv, poh, pmlph);

    // 3) routing
    ln_f_kernel<<<BATCH, 256>>>(px, pfeat, norm_w, norm_b, (long long)S1 * DMODEL, DMODEL);
    pool_stats_kernel<<<POOL, 256>>>(variance);
    logwn_kernel<<<1, 1>>>(frequency);
    quad_kernel<<<dim3(BATCH, POOL), 256>>>(key_pool, inv_variance);
    topk_kernel<<<1, 32>>>();

    // 4) splice prompts (S=222)
    build_sx_kernel<<<(BATCH * SMAX * DMODEL + 255) / 256, 256>>>(prompts, pos_embed);

    // 5) second ViT pass (S=222)
    run_vit(SMAX, BATCH * SMAX, ln1_w, ln1_b, pwq, qkv_b, pwp, proj_b,
            ln2_w, ln2_b, pw1, fc1_b, pw2, fc2_b, px, phh, pqkv, poh, pmlph);

    // 6) final LN, mean over prompt tokens, head
    ln_f_kernel<<<BATCH * SMAX, 256>>>(px, ph, norm_w, norm_b, DMODEL, DMODEL);
    feat_kernel<<<(BATCH * DMODEL + 255) / 256, 256>>>();
    head_kernel<<<(BATCH * NCLS + 255) / 256, 256>>>(head_w, head_b, (float*)d_out);
}

// round 16
// speedup vs baseline: 2.0922x; 1.1182x over previous
#include <cuda_runtime.h>
#include <cuda_fp16.h>
#include <cstdint>

#define BATCH  32
#define SMAX   222
#define S1     197
#define DMODEL 768
#define NLAYER 12
#define NHEAD  12
#define HDIM   64
#define MLPD   3072
#define POOL   10
#define SEL    5
#define PLEN   5
#define NCLS   100
#define PSTRIDE 224

// ---------------- scratch (static device allocations; harness-legal) ----------------
__device__ float  g_x   [BATCH * SMAX * DMODEL];
__device__ float  g_x0  [BATCH * S1   * DMODEL];
__device__ float  g_h   [BATCH * SMAX * DMODEL];     // final-LN output (fp32)
__device__ __half g_hh  [BATCH * SMAX * DMODEL];     // in-layer LN output (half)
__device__ float  g_qkv [BATCH * SMAX * 3 * DMODEL];
__device__ __half g_oh  [BATCH * SMAX * DMODEL];     // attention output (half)
__device__ float  g_o   [BATCH * SMAX * DMODEL];     // patch-embed GEMM output (fp32)
__device__ __half g_mlph[BATCH * SMAX * MLPD];       // patchify / GELU output (half)
__device__ float  g_p   [BATCH * NHEAD * PSTRIDE * PSTRIDE];
__device__ float  g_feat[BATCH * DMODEL];
__device__ float  g_score[BATCH * POOL];
__device__ float  g_lognorm[POOL];
__device__ float  g_logwn[POOL];
__device__ int    g_topk[BATCH * SEL];

// fp16, TRANSPOSED ([N][K] K-major) weight copies, built once per launch
__device__ __half g_wq [NLAYER * DMODEL * 3 * DMODEL];
__device__ __half g_wp [NLAYER * DMODEL * DMODEL];
__device__ __half g_w1 [NLAYER * DMODEL * MLPD];
__device__ __half g_w2 [NLAYER * MLPD * DMODEL];
__device__ __half g_wpc[DMODEL * DMODEL];

// ---------------- reductions (blockDim == 256 assumed) ----------------
__device__ __forceinline__ float block_sum256(float v, float* red) {
    int lane = threadIdx.x & 31, wid = threadIdx.x >> 5;
    #pragma unroll
    for (int o = 16; o; o >>= 1) v += __shfl_xor_sync(0xffffffffu, v, o);
    if (lane == 0) red[wid] = v;
    __syncthreads();
    float r = (lane < 8) ? red[lane] : 0.f;
    #pragma unroll
    for (int o = 4; o; o >>= 1) r += __shfl_xor_sync(0xffffffffu, r, o);
    r = __shfl_sync(0xffffffffu, r, 0);
    __syncthreads();
    return r;
}

__device__ __forceinline__ float block_max256(float v, float* red) {
    int lane = threadIdx.x & 31, wid = threadIdx.x >> 5;
    #pragma unroll
    for (int o = 16; o; o >>= 1) v = fmaxf(v, __shfl_xor_sync(0xffffffffu, v, o));
    if (lane == 0) red[wid] = v;
    __syncthreads();
    float r = (lane < 8) ? red[lane] : -1e30f;
    #pragma unroll
    for (int o = 4; o; o >>= 1) r = fmaxf(r, __shfl_xor_sync(0xffffffffu, r, o));
    r = __shfl_sync(0xffffffffu, r, 0);
    __syncthreads();
    return r;
}

// ---------------- mma / cp.async / ldmatrix helpers ----------------
__device__ __forceinline__ void mma_f16(float* c, const uint32_t* a, uint32_t b0, uint32_t b1) {
    asm volatile(
        "mma.sync.aligned.m16n8k16.row.col.f32.f16.f16.f32 "
        "{%0,%1,%2,%3}, {%4,%5,%6,%7}, {%8,%9}, {%0,%1,%2,%3};"
        : "+f"(c[0]), "+f"(c[1]), "+f"(c[2]), "+f"(c[3])
        : "r"(a[0]), "r"(a[1]), "r"(a[2]), "r"(a[3]), "r"(b0), "r"(b1));
}

__device__ __forceinline__ void ldsm_x4(uint32_t& r0, uint32_t& r1, uint32_t& r2, uint32_t& r3,
                                        uint32_t addr) {
    asm volatile("ldmatrix.sync.aligned.m8n8.x4.shared.b16 {%0,%1,%2,%3}, [%4];"
                 : "=r"(r0), "=r"(r1), "=r"(r2), "=r"(r3) : "r"(addr));
}

__device__ __forceinline__ void cp_async16(void* smem_dst, const void* gsrc, int src_bytes) {
    unsigned sa = (unsigned)__cvta_generic_to_shared(smem_dst);
    asm volatile("cp.async.cg.shared.global [%0], [%1], 16, %2;"
                 :: "r"(sa), "l"(gsrc), "r"(src_bytes));
}
__device__ __forceinline__ void cp_commit() {
    asm volatile("cp.async.commit_group;");
}

// ---------------- weight transpose + fp16 round: dst[n*K+k] = h(src[k*N+n]) -------
__global__ void transpose_h_kernel(const float* __restrict__ src, __half* __restrict__ dst,
                                   int K, int N)
{
    __shared__ float tile[32][33];
    int l = blockIdx.z;
    const float* s = src + (size_t)l * K * N;
    __half* d = dst + (size_t)l * K * N;
    int k0 = blockIdx.y * 32, n0 = blockIdx.x * 32;
    for (int i = threadIdx.y; i < 32; i += 8)
        tile[i][threadIdx.x] = s[(size_t)(k0 + i) * N + n0 + threadIdx.x];
    __syncthreads();
    for (int i = threadIdx.y; i < 32; i += 8)
        d[(size_t)(n0 + i) * K + k0 + threadIdx.x] = __float2half_rn(tile[threadIdx.x][i]);
}

// ---------------- pipelined fp16 tensor-core GEMM (ldmatrix, TBK=64) --------------
// C[M,N] = A[M,K] @ WT[N,K]^T + bias.  A, WT fp16; accumulate fp32.
// mode 0: store fp32; mode 1: GELU -> store HALF (C is __half*); mode 2: += fp32.
// Requires K % 64 == 0, N % 128 == 0; M guarded.
#define TBM 128
#define TBN 128
#define TBK 64
#define HPITCH 72    // halves per row (64 + 8 pad); 144B rows: LDSM rows conflict-free (4r mod 32)
#define GEMM_SMEM (4 * TBM * HPITCH * 2)   // A[2] + W[2] buffers, 73728 B

__global__ void __launch_bounds__(256) hgemm_kernel(
    const __half* __restrict__ A, const __half* __restrict__ WT,
    const float* __restrict__ bias, void* __restrict__ Cv,
    int M, int N, int K, int mode)
{
    extern __shared__ __half hsm[];
    __half* As = hsm;                        // [2][TBM*HPITCH]
    __half* Ws = hsm + 2 * TBM * HPITCH;     // [2][TBN*HPITCH]

    int tid  = threadIdx.x;
    int warp = tid >> 5, lane = tid & 31;
    int g = lane >> 2, tig = lane & 3;
    int wm = (warp & 1) * 64;
    int wn = (warp >> 1) * 32;
    int row0 = blockIdx.y * TBM;
    int col0 = blockIdx.x * TBN;

    uint32_t a_off = (uint32_t)(((lane & 15) * HPITCH + (lane >> 4) * 8) * 2);
    uint32_t b_off = (uint32_t)((((lane & 7) + ((lane >> 4) & 1) * 8) * HPITCH + ((lane >> 3) & 1) * 8) * 2);

    float acc[4][4][4];
    #pragma unroll
    for (int mt = 0; mt < 4; mt++)
        #pragma unroll
        for (int nt = 0; nt < 4; nt++)
            #pragma unroll
            for (int i = 0; i < 4; i++) acc[mt][nt][i] = 0.f;

    // per tile: A = 128 rows x 64 halves = 1024 16B-chunks; same for W
    auto load_tiles = [&](int k0, int buf) {
        __half* Ab = As + buf * TBM * HPITCH;
        __half* Wb = Ws + buf * TBN * HPITCH;
        #pragma unroll
        for (int i = 0; i < 4; i++) {
            int slot = tid + i * 256;          // 0..1023
            int r = slot >> 3, c = slot & 7;
            int gm = row0 + r;
            const __half* src = A + (size_t)gm * K + k0 + c * 8;
            cp_async16(&Ab[r * HPITCH + c * 8], src, (gm < M) ? 16 : 0);
        }
        #pragma unroll
        for (int i = 0; i < 4; i++) {
            int slot = tid + i * 256;
            int n = slot >> 3, c = slot & 7;
            const __half* src = WT + (size_t)(col0 + n) * K + k0 + c * 8;
            cp_async16(&Wb[n * HPITCH + c * 8], src, 16);
        }
        cp_commit();
    };

    int T = K / TBK;
    load_tiles(0, 0);

    for (int t = 0; t < T; t++) {
        int buf = t & 1;
        if (t + 1 < T) {
            load_tiles((t + 1) * TBK, (t + 1) & 1);
            asm volatile("cp.async.wait_group 1;");
        } else {
            asm volatile("cp.async.wait_group 0;");
        }
        __syncthreads();

        uint32_t abase = (uint32_t)__cvta_generic_to_shared(As + buf * TBM * HPITCH);
        uint32_t bbase = (uint32_t)__cvta_generic_to_shared(Ws + buf * TBN * HPITCH);
        #pragma unroll
        for (int ks = 0; ks < 4; ks++) {       // four k16 steps per 64-K tile
            int kk = ks * 16;
            uint32_t af[4][4];
            #pragma unroll
            for (int mt = 0; mt < 4; mt++) {
                uint32_t addr = abase + (uint32_t)(((wm + mt * 16) * HPITCH + kk) * 2) + a_off;
                ldsm_x4(af[mt][0], af[mt][1], af[mt][2], af[mt][3], addr);
            }
            uint32_t b0[4], b1[4];
            #pragma unroll
            for (int p = 0; p < 2; p++) {
                uint32_t addr = bbase + (uint32_t)(((wn + p * 16) * HPITCH + kk) * 2) + b_off;
                ldsm_x4(b0[p * 2], b1[p * 2], b0[p * 2 + 1], b1[p * 2 + 1], addr);
            }
            #pragma unroll
            for (int nt = 0; nt < 4; nt++)
                #pragma unroll
                for (int mt = 0; mt < 4; mt++)
                    mma_f16(acc[mt][nt], af[mt], b0[nt], b1[nt]);
        }
        __syncthreads();
    }

    float* Cf = (float*)Cv;
    __half* Ch = (__half*)Cv;
    #pragma unroll
    for (int mt = 0; mt < 4; mt++) {
        #pragma unroll
        for (int nt = 0; nt < 4; nt++) {
            int gn = col0 + wn + nt * 8 + tig * 2;
            #pragma unroll
            for (int half_ = 0; half_ < 2; half_++) {
                int gm = row0 + wm + mt * 16 + g + half_ * 8;
                if (gm >= M) continue;
                #pragma unroll
                for (int cc = 0; cc < 2; cc++) {
                    float v = acc[mt][nt][half_ * 2 + cc] + bias[gn + cc];
                    size_t off = (size_t)gm * N + gn + cc;
                    if (mode == 1) {
                        v = 0.5f * v * (1.0f + erff(v * 0.70710678118654752f));
                        Ch[off] = __float2half_rn(v);
                    } else if (mode == 2) {
                        Cf[off] += v;
                    } else {
                        Cf[off] = v;
                    }
                }
            }
        }
    }
}

// ---------------- LayerNorm over 768 ----------------
__global__ void ln_h_kernel(const float* __restrict__ in, __half* __restrict__ out,
                            const float* __restrict__ w, const float* __restrict__ b)
{
    __shared__ float red[8];
    const float* x = in + (long long)blockIdx.x * DMODEL;
    __half* y = out + (long long)blockIdx.x * DMODEL;
    int t = threadIdx.x;
    float v0 = x[t], v1 = x[t + 256], v2 = x[t + 512];
    float mean = block_sum256(v0 + v1 + v2, red) * (1.f / 768.f);
    float d0 = v0 - mean, d1 = v1 - mean, d2 = v2 - mean;
    float var = block_sum256(d0 * d0 + d1 * d1 + d2 * d2, red) * (1.f / 768.f);
    float rstd = rsqrtf(var + 1e-6f);
    y[t]       = __float2half_rn(d0 * rstd * w[t]       + b[t]);
    y[t + 256] = __float2half_rn(d1 * rstd * w[t + 256] + b[t + 256]);
    y[t + 512] = __float2half_rn(d2 * rstd * w[t + 512] + b[t + 512]);
}

__global__ void ln_f_kernel(const float* __restrict__ in, float* __restrict__ out,
                            const float* __restrict__ w, const float* __restrict__ b,
                            long long in_stride, long long out_stride)
{
    __shared__ float red[8];
    const float* x = in + (long long)blockIdx.x * in_stride;
    float* y = out + (long long)blockIdx.x * out_stride;
    int t = threadIdx.x;
    float v0 = x[t], v1 = x[t + 256], v2 = x[t + 512];
    float mean = block_sum256(v0 + v1 + v2, red) * (1.f / 768.f);
    float d0 = v0 - mean, d1 = v1 - mean, d2 = v2 - mean;
    float var = block_sum256(d0 * d0 + d1 * d1 + d2 * d2, red) * (1.f / 768.f);
    float rstd = rsqrtf(var + 1e-6f);
    y[t]       = d0 * rstd * w[t]       + b[t];
    y[t + 256] = d1 * rstd * w[t + 256] + b[t + 256];
    y[t + 512] = d2 * rstd * w[t + 512] + b[t + 512];
}

// ---------------- attention: fused score+softmax, then pv ----------------
#define SPAD 68
#define SROWP 228   // row pitch for score buffer (224 + 4, 16B-aligned)
#define SCORE_SMEM ((32 * SPAD + 64 * SPAD + 32 * SROWP) * 4)   // 55296 B

__global__ void __launch_bounds__(256) score_softmax_kernel(const float* __restrict__ qkv, int S)
{
    extern __shared__ float sm[];
    float* Qs   = sm;                       // [32][SPAD]
    float* KsT  = sm + 32 * SPAD;           // [64][SPAD]  ([d][k])
    float* Srow = sm + 32 * SPAD + 64 * SPAD; // [32][SROWP]

    int q0 = blockIdx.x * 32, h = blockIdx.y, b = blockIdx.z;
    int tid = threadIdx.x;
    int q = tid >> 3, kg = tid & 7;
    const float* base = qkv + (size_t)b * S * (3 * DMODEL) + h * HDIM;
    float* prow = g_p + (((size_t)b * NHEAD + h) * PSTRIDE) * PSTRIDE;

    // init score row buffer to -inf (covers k >= S)
    for (int i = tid; i < 32 * SROWP; i += 256) Srow[i] = -1e30f;

    // load Q tile [32 x 64]
    #pragma unroll
    for (int i = 0; i < 2; i++) {
        int slot = tid + i * 256;
        int r = slot >> 4, c4 = (slot & 15) * 4;
        int gq = q0 + r;
        float4 v = make_float4(0.f, 0.f, 0.f, 0.f);
        if (gq < S) v = *reinterpret_cast<const float4*>(&base[(size_t)gq * (3 * DMODEL) + c4]);
        *reinterpret_cast<float4*>(&Qs[r * SPAD + c4]) = v;
    }

    int ntile = (S + 63) >> 6;
    for (int kt = 0; kt < ntile; kt++) {
        int k0 = kt * 64;
        #pragma unroll
        for (int i = 0; i < 4; i++) {
            int slot = tid + i * 256;
            int r = slot >> 4, c4 = (slot & 15) * 4;
            int gk = k0 + r;
            float4 v = make_float4(0.f, 0.f, 0.f, 0.f);
            if (gk < S) v = *reinterpret_cast<const float4*>(&base[(size_t)gk * (3 * DMODEL) + DMODEL + c4]);
            KsT[(c4 + 0) * SPAD + r] = v.x;
            KsT[(c4 + 1) * SPAD + r] = v.y;
            KsT[(c4 + 2) * SPAD + r] = v.z;
            KsT[(c4 + 3) * SPAD + r] = v.w;
        }
        __syncthreads();

        float acc[8];
        #pragma unroll
        for (int j = 0; j < 8; j++) acc[j] = 0.f;
        #pragma unroll
        for (int d = 0; d < HDIM; d++) {
            float qa = Qs[q * SPAD + d];
            float4 kv0 = *reinterpret_cast<const float4*>(&KsT[d * SPAD + kg * 8]);
            float4 kv1 = *reinterpret_cast<const float4*>(&KsT[d * SPAD + kg * 8 + 4]);
            acc[0] += qa * kv0.x; acc[1] += qa * kv0.y;
            acc[2] += qa * kv0.z; acc[3] += qa * kv0.w;
            acc[4] += qa * kv1.x; acc[5] += qa * kv1.y;
            acc[6] += qa * kv1.z; acc[7] += qa * kv1.w;
        }
        #pragma unroll
        for (int j = 0; j < 8; j++) {
            int gk = k0 + kg * 8 + j;
            if (gk < S) Srow[q * SROWP + gk] = acc[j] * 0.125f;
        }
        __syncthreads();
    }

    // softmax per row: 8 threads (kg) per row q, 28 strided values each
    float vals[28];
    float mx = -1e30f;
    #pragma unroll
    for (int i = 0; i < 28; i++) {
        vals[i] = Srow[q * SROWP + kg + i * 8];
        mx = fmaxf(mx, vals[i]);
    }
    #pragma unroll
    for (int o = 4; o; o >>= 1) mx = fmaxf(mx, __shfl_xor_sync(0xffffffffu, mx, o, 8));
    float sum = 0.f;
    #pragma unroll
    for (int i = 0; i < 28; i++) { vals[i] = expf(vals[i] - mx); sum += vals[i]; }
    #pragma unroll
    for (int o = 4; o; o >>= 1) sum += __shfl_xor_sync(0xffffffffu, sum, o, 8);
    float inv = 1.f / sum;

    int gq = q0 + q;
    if (gq < S) {
        float* pr = prow + (size_t)gq * PSTRIDE;
        #pragma unroll
        for (int i = 0; i < 28; i++) pr[kg + i * 8] = vals[i] * inv;
    }
}

// pv: output HALF (feeds proj GEMM)
__global__ void __launch_bounds__(256) pv_kernel(const float* __restrict__ qkv,
                                                 __half* __restrict__ o, int S)
{
    __shared__ float Ps[32][SPAD];
    __shared__ float Vs[64][SPAD];
    int q0 = blockIdx.x * 32, h = blockIdx.y, b = blockIdx.z;
    int tid = threadIdx.x;
    int q = tid >> 3, dg = tid & 7;
    const float* vbase = qkv + (size_t)b * S * (3 * DMODEL) + 2 * DMODEL + h * HDIM;
    const float* prow = g_p + (((size_t)b * NHEAD + h) * PSTRIDE) * PSTRIDE;

    float acc[8];
    #pragma unroll
    for (int j = 0; j < 8; j++) acc[j] = 0.f;

    int ntile = (S + 63) >> 6;
    for (int kt = 0; kt < ntile; kt++) {
        int k0 = kt * 64;
        #pragma unroll
        for (int i = 0; i < 2; i++) {
            int slot = tid + i * 256;
            int r = slot >> 4, c4 = (slot & 15) * 4;
            int gq = q0 + r;
            float4 v = make_float4(0.f, 0.f, 0.f, 0.f);
            if (gq < S) {
                #pragma unroll
                for (int c = 0; c < 4; c++) {
                    int gk = k0 + c4 + c;
                    ((float*)&v)[c] = (gk < S) ? prow[(size_t)gq * PSTRIDE + gk] : 0.f;
                }
            }
            *reinterpret_cast<float4*>(&Ps[r][c4]) = v;
        }
        #pragma unroll
        for (int i = 0; i < 4; i++) {
            int slot = tid + i * 256;
            int r = slot >> 4, c4 = (slot & 15) * 4;
            int gk = k0 + r;
            float4 v = make_float4(0.f, 0.f, 0.f, 0.f);
            if (gk < S) v = *reinterpret_cast<const float4*>(&vbase[(size_t)gk * (3 * DMODEL) + c4]);
            *reinterpret_cast<float4*>(&Vs[r][c4]) = v;
        }
        __syncthreads();

        #pragma unroll
        for (int k = 0; k < 64; k++) {
            float p = Ps[q][k];
            float4 v0 = *reinterpret_cast<const float4*>(&Vs[k][dg * 8]);
            float4 v1 = *reinterpret_cast<const float4*>(&Vs[k][dg * 8 + 4]);
            acc[0] += p * v0.x; acc[1] += p * v0.y;
            acc[2] += p * v0.z; acc[3] += p * v0.w;
            acc[4] += p * v1.x; acc[5] += p * v1.y;
            acc[6] += p * v1.z; acc[7] += p * v1.w;
        }
        __syncthreads();
    }

    int gq = q0 + q;
    if (gq < S) {
        __half* ow = o + ((size_t)(b * S + gq)) * DMODEL + h * HDIM + dg * 8;
        #pragma unroll
        for (int j = 0; j < 8; j++) ow[j] = __float2half_rn(acc[j]);
    }
}

// ---------------- patchify + embedding ----------------
__global__ void patchify_kernel(const float* __restrict__ in)
{
    size_t i = (size_t)blockIdx.x * 256 + threadIdx.x;
    if (i >= (size_t)BATCH * 196 * DMODEL) return;
    int v = (int)(i % DMODEL);
    size_t t = i / DMODEL;
    int p = (int)(t % 196);
    int b = (int)(t / 196);
    int c = v >> 8;
    int py = (v & 255) >> 4;
    int px = v & 15;
    int gy = p / 14, gx = p % 14;
    g_mlph[i] = __float2half_rn(in[(((size_t)b * 3 + c) * 224 + gy * 16 + py) * 224 + gx * 16 + px]);
}

__global__ void embed_kernel(const float* __restrict__ cls, const float* __restrict__ pos)
{
    size_t i = (size_t)blockIdx.x * 256 + threadIdx.x;
    if (i >= (size_t)BATCH * S1 * DMODEL) return;
    int d = (int)(i % DMODEL);
    size_t t = i / DMODEL;
    int s = (int)(t % S1);
    int b = (int)(t / S1);
    float v;
    if (s == 0) v = cls[d] + pos[d];
    else        v = g_o[((size_t)b * 196 + (s - 1)) * DMODEL + d] + pos[(size_t)s * DMODEL + d];
    g_x[i] = v;
    g_x0[i] = v;
}

// ---------------- routing ----------------
__global__ void pool_stats_kernel(const float* __restrict__ var)
{
    __shared__ float red[8];
    int p = blockIdx.x;
    const float* v = var + (size_t)p * DMODEL * DMODEL;
    float s = 0.f;
    for (int i = threadIdx.x; i < DMODEL * DMODEL; i += 256) { float t = v[i]; s += t * t; }
    float tot = block_sum256(s, red);
    if (threadIdx.x == 0) g_lognorm[p] = 0.25f * logf(tot);
}

__global__ void logwn_kernel(const float* __restrict__ freq)
{
    float m = freq[0];
    for (int i = 1; i < POOL; i++) m = fmaxf(m, freq[i]);
    float w[POOL]; float ss = 0.f;
    for (int i = 0; i < POOL; i++) { w[i] = m - freq[i]; ss += w[i] * w[i]; }
    float nz = fmaxf(sqrtf(ss), 1e-12f);
    for (int i = 0; i < POOL; i++) g_logwn[i] = logf(fmaxf(w[i] / nz, 1e-30f));
}

__global__ void quad_kernel(const float* __restrict__ keys, const float* __restrict__ inv_var)
{
    __shared__ float diff[DMODEL];
    __shared__ float red[8];
    int b = blockIdx.x, p = blockIdx.y;
    for (int i = threadIdx.x; i < DMODEL; i += 256)
        diff[i] = g_feat[b * DMODEL + i] - keys[p * DMODEL + i];
    __syncthreads();
    const float* M = inv_var + (size_t)p * DMODEL * DMODEL;
    float acc = 0.f;
    #pragma unroll
    for (int ei = 0; ei < 3; ei++) {
        int e = threadIdx.x + ei * 256;
        float inner = 0.f;
        for (int d = 0; d < DMODEL; d++)
            inner += diff[d] * M[(size_t)d * DMODEL + e];
        acc += inner * diff[e];
    }
    float quad = block_sum256(acc, red);
    if (threadIdx.x == 0)
        g_score[b * POOL + p] = -0.5f * quad + g_lognorm[p] + g_logwn[p];
}

__global__ void topk_kernel()
{
    int b = threadIdx.x;
    if (b >= BATCH) return;
    float s[POOL]; bool used[POOL];
    for (int p = 0; p < POOL; p++) { s[p] = g_score[b * POOL + p]; used[p] = false; }
    for (int i = 0; i < SEL; i++) {
        int best = 0; float bv = 3.0e38f;
        for (int p = 0; p < POOL; p++)
            if (!used[p] && s[p] < bv) { bv = s[p]; best = p; }
        used[best] = true;
        g_topk[b * SEL + i] = best;
    }
}

__global__ void build_sx_kernel(const float* __restrict__ prompts, const float* __restrict__ pos)
{
    size_t i = (size_t)blockIdx.x * 256 + threadIdx.x;
    if (i >= (size_t)BATCH * SMAX * DMODEL) return;
    int d = (int)(i % DMODEL);
    size_t t = i / DMODEL;
    int s = (int)(t % SMAX);
    int b = (int)(t / SMAX);
    float v;
    if (s == 0) {
        v = g_x0[(size_t)b * S1 * DMODEL + d];
    } else if (s <= SEL * PLEN) {
        int idx = s - 1;
        int pi = idx / PLEN, j = idx % PLEN;
        int pool = g_topk[b * SEL + pi];
        v = prompts[((size_t)pool * PLEN + j) * DMODEL + d] + pos[d];
    } else {
        v = g_x0[((size_t)b * S1 + (s - SEL * PLEN)) * DMODEL + d];
    }
    g_x[i] = v;
}

// ---------------- epilogue ----------------
__global__ void feat_kernel()
{
    int i = blockIdx.x * 256 + threadIdx.x;
    if (i >= BATCH * DMODEL) return;
    int b = i / DMODEL, d = i % DMODEL;
    float s = 0.f;
    for (int t = 1; t <= SEL * PLEN; t++)
        s += g_h[((size_t)b * SMAX + t) * DMODEL + d];
    g_feat[i] = s * (1.f / (SEL * PLEN));
}

__global__ void head_kernel(const float* __restrict__ hw, const float* __restrict__ hb,
                            float* __restrict__ out)
{
    int i = blockIdx.x * 256 + threadIdx.x;
    if (i >= BATCH * NCLS) return;
    int b = i / NCLS, n = i % NCLS;
    float acc = hb[n];
    for (int k = 0; k < DMODEL; k++) acc += g_feat[b * DMODEL + k] * hw[k * NCLS + n];
    out[i] = acc;
}

// ---------------- host orchestration ----------------
static void run_vit(int S, int M,
    const float* ln1w, const float* ln1b, const __half* qkvw, const float* qkvb,
    const __half* pw, const float* pb, const float* ln2w, const float* ln2b,
    const __half* f1w, const float* f1b, const __half* f2w, const float* f2b,
    float* px, __half* phh, float* pqkv, __half* poh, __half* pmlph)
{
    int gy = (M + TBM - 1) / TBM;
    int qt = (S + 31) / 32;
    for (int l = 0; l < NLAYER; l++) {
        ln_h_kernel<<<M, 256>>>(px, phh, ln1w + (size_t)l * DMODEL, ln1b + (size_t)l * DMODEL);
        hgemm_kernel<<<dim3(3 * DMODEL / TBN, gy), 256, GEMM_SMEM>>>(phh, qkvw + (size_t)l * DMODEL * 3 * DMODEL,
                                                          qkvb + (size_t)l * 3 * DMODEL, pqkv, M, 3 * DMODEL, DMODEL, 0);
        score_softmax_kernel<<<dim3(qt, NHEAD, BATCH), 256, SCORE_SMEM>>>(pqkv, S);
        pv_kernel<<<dim3(qt, NHEAD, BATCH), 256>>>(pqkv, poh, S);
        hgemm_kernel<<<dim3(DMODEL / TBN, gy), 256, GEMM_SMEM>>>(poh, pw + (size_t)l * DMODEL * DMODEL,
                                                      pb + (size_t)l * DMODEL, px, M, DMODEL, DMODEL, 2);
        ln_h_kernel<<<M, 256>>>(px, phh, ln2w + (size_t)l * DMODEL, ln2b + (size_t)l * DMODEL);
        hgemm_kernel<<<dim3(MLPD / TBN, gy), 256, GEMM_SMEM>>>(phh, f1w + (size_t)l * DMODEL * MLPD,
                                                    f1b + (size_t)l * MLPD, pmlph, M, MLPD, DMODEL, 1);
        hgemm_kernel<<<dim3(DMODEL / TBN, gy), 256, GEMM_SMEM>>>(pmlph, f2w + (size_t)l * MLPD * DMODEL,
                                                      f2b + (size_t)l * DMODEL, px, M, DMODEL, MLPD, 2);
    }
}

extern "C" void kernel_launch(void* const* d_in, const int* in_sizes, int n_in,
                              void* d_out, int out_size)
{
    const float* inputs    = (const float*)d_in[0];
    const float* patch_w   = (const float*)d_in[1];
    const float* patch_b   = (const float*)d_in[2];
    const float* cls_token = (const float*)d_in[3];
    const float* pos_embed = (const float*)d_in[4];
    const float* ln1_w = (const float*)d_in[5];
    const float* ln1_b = (const float*)d_in[6];
    const float* qkv_w = (const float*)d_in[7];
    const float* qkv_b = (const float*)d_in[8];
    const float* proj_w = (const float*)d_in[9];
    const float* proj_b = (const float*)d_in[10];
    const float* ln2_w = (const float*)d_in[11];
    const float* ln2_b = (const float*)d_in[12];
    const float* fc1_w = (const float*)d_in[13];
    const float* fc1_b = (const float*)d_in[14];
    const float* fc2_w = (const float*)d_in[15];
    const float* fc2_b = (const float*)d_in[16];
    const float* norm_w = (const float*)d_in[17];
    const float* norm_b = (const float*)d_in[18];
    const float* head_w = (const float*)d_in[19];
    const float* head_b = (const float*)d_in[20];
    const float* key_pool = (const float*)d_in[21];
    const float* frequency = (const float*)d_in[22];
    const float* prompts = (const float*)d_in[23];
    const float* variance = (const float*)d_in[24];
    const float* inv_variance = (const float*)d_in[25];

    static bool attr_set = false;
    if (!attr_set) {
        cudaFuncSetAttribute(hgemm_kernel, cudaFuncAttributeMaxDynamicSharedMemorySize, GEMM_SMEM);
        cudaFuncSetAttribute(score_softmax_kernel, cudaFuncAttributeMaxDynamicSharedMemorySize, SCORE_SMEM);
        attr_set = true;
    }

    float *px, *ph, *pqkv, *po, *pfeat;
    __half *phh, *poh, *pmlph;
    __half *pwq, *pwp, *pw1, *pw2, *pwpc;
    cudaGetSymbolAddress((void**)&px,    g_x);
    cudaGetSymbolAddress((void**)&ph,    g_h);
    cudaGetSymbolAddress((void**)&phh,   g_hh);
    cudaGetSymbolAddress((void**)&pqkv,  g_qkv);
    cudaGetSymbolAddress((void**)&po,    g_o);
    cudaGetSymbolAddress((void**)&poh,   g_oh);
    cudaGetSymbolAddress((void**)&pmlph, g_mlph);
    cudaGetSymbolAddress((void**)&pfeat, g_feat);
    cudaGetSymbolAddress((void**)&pwq,   g_wq);
    cudaGetSymbolAddress((void**)&pwp,   g_wp);
    cudaGetSymbolAddress((void**)&pw1,   g_w1);
    cudaGetSymbolAddress((void**)&pw2,   g_w2);
    cudaGetSymbolAddress((void**)&pwpc,  g_wpc);

    // 0) weight prep: transpose to [N][K] + fp16 round (once per launch)
    {
        dim3 blk(32, 8);
        transpose_h_kernel<<<dim3(3 * DMODEL / 32, DMODEL / 32, NLAYER), blk>>>(qkv_w, pwq, DMODEL, 3 * DMODEL);
        transpose_h_kernel<<<dim3(DMODEL / 32, DMODEL / 32, NLAYER), blk>>>(proj_w, pwp, DMODEL, DMODEL);
        transpose_h_kernel<<<dim3(MLPD / 32, DMODEL / 32, NLAYER), blk>>>(fc1_w, pw1, DMODEL, MLPD);
        transpose_h_kernel<<<dim3(DMODEL / 32, MLPD / 32, NLAYER), blk>>>(fc2_w, pw2, MLPD, DMODEL);
        transpose_h_kernel<<<dim3(DMODEL / 32, DMODEL / 32, 1), blk>>>(patch_w, pwpc, DMODEL, DMODEL);
    }

    // 1) patch embed
    patchify_kernel<<<(BATCH * 196 * DMODEL + 255) / 256, 256>>>(inputs);
    hgemm_kernel<<<dim3(DMODEL / TBN, (BATCH * 196 + TBM - 1) / TBM), 256, GEMM_SMEM>>>(
        pmlph, pwpc, patch_b, po, BATCH * 196, DMODEL, DMODEL, 0);
    embed_kernel<<<(BATCH * S1 * DMODEL + 255) / 256, 256>>>(cls_token, pos_embed);

    // 2) first ViT pass (S=197)
    run_vit(S1, BATCH * S1, ln1_w, ln1_b, pwq, qkv_b, pwp, proj_b,
            ln2_w, ln2_b, pw1, fc1_b, pw2, fc2_b, px, phh, pqkv, poh, pmlph);

    // 3) routing
    ln_f_kernel<<<BATCH, 256>>>(px, pfeat, norm_w, norm_b, (long long)S1 * DMODEL, DMODEL);
    pool_stats_kernel<<<POOL, 256>>>(variance);
    logwn_kernel<<<1, 1>>>(frequency);
    quad_kernel<<<dim3(BATCH, POOL), 256>>>(key_pool, inv_variance);
    topk_kernel<<<1, 32>>>();

    // 4) splice prompts (S=222)
    build_sx_kernel<<<(BATCH * SMAX * DMODEL + 255) / 256, 256>>>(prompts, pos_embed);

    // 5) second ViT pass (S=222)
    run_vit(SMAX, BATCH * SMAX, ln1_w, ln1_b, pwq, qkv_b, pwp, proj_b,
            ln2_w, ln2_b, pw1, fc1_b, pw2, fc2_b, px, phh, pqkv, poh, pmlph);

    // 6) final LN, mean over prompt tokens, head
    ln_f_kernel<<<BATCH * SMAX, 256>>>(px, ph, norm_w, norm_b, DMODEL, DMODEL);
    feat_kernel<<<(BATCH * DMODEL + 255) / 256, 256>>>();
    head_kernel<<<(BATCH * NCLS + 255) / 256, 256>>>(head_w, head_b, (float*)d_out);
}